// round 12
// baseline (speedup 1.0000x reference)
#include <cuda_runtime.h>
#include <cuda_bf16.h>
#include <cstdint>

#define NG   2048
#define MAXN 500000
#define BN_EPS 1e-5f

typedef unsigned long long ull;

// ---------------- scratch (device globals; no allocation allowed) ----------------
__device__ __align__(16) __nv_bfloat16 g_hhi[(size_t)MAXN * 128];
__device__ __align__(16) __nv_bfloat16 g_hlo[(size_t)MAXN * 128];
__device__ __align__(16) float g_y[(size_t)MAXN * 128];
__device__ __align__(16) float g_lam1[NG * 128];
__device__ __align__(16) float g_lam2[NG * 128];
__device__ __align__(16) float g_psum[NG * 128];
__device__ __align__(16) float g_psq[NG * 128];
__device__ __align__(16) float g_scale[128];
__device__ __align__(16) float g_shift[128];
__device__ int g_seg[NG + 1];

// ---------------- helpers ----------------
__device__ __forceinline__ uint32_t smaddr(const void* p) {
    return (uint32_t)__cvta_generic_to_shared(p);
}
__device__ __forceinline__ void cp16(uint32_t d, const void* s, int n) {
    asm volatile("cp.async.ca.shared.global [%0], [%1], 16, %2;\n" :: "r"(d), "l"(s), "r"(n));
}
#define CP_COMMIT() asm volatile("cp.async.commit_group;\n" ::: "memory")
#define CP_WAIT0()  asm volatile("cp.async.wait_group 0;\n" ::: "memory")

__device__ __forceinline__ void mma_bf16(float* d, const uint32_t* a, const uint32_t* b) {
    asm volatile(
        "mma.sync.aligned.m16n8k16.row.col.f32.bf16.bf16.f32 "
        "{%0,%1,%2,%3}, {%4,%5,%6,%7}, {%8,%9}, {%0,%1,%2,%3};"
        : "+f"(d[0]), "+f"(d[1]), "+f"(d[2]), "+f"(d[3])
        : "r"(a[0]), "r"(a[1]), "r"(a[2]), "r"(a[3]), "r"(b[0]), "r"(b[1]));
}
__device__ __forceinline__ void ldsm4(uint32_t* r, uint32_t a) {
    asm volatile("ldmatrix.sync.aligned.m8n8.x4.shared.b16 {%0,%1,%2,%3}, [%4];"
        : "=r"(r[0]), "=r"(r[1]), "=r"(r[2]), "=r"(r[3]) : "r"(a));
}

__device__ __forceinline__ void bsplit2(float a, float b, uint32_t& hi, uint32_t& lo) {
    __nv_bfloat162 h = __floats2bfloat162_rn(a, b);
    hi = *reinterpret_cast<uint32_t*>(&h);
    float ra = a - __bfloat162float(h.x);
    float rb = b - __bfloat162float(h.y);
    __nv_bfloat162 l = __floats2bfloat162_rn(ra, rb);
    lo = *reinterpret_cast<uint32_t*>(&l);
}

// ---- gemm1 smem map (64-row tiles, ROWB=304, K=144) ----
#define ROWB 304
#define OFF_BH 512
#define OFF_BL (OFF_BH + 38912)
#define OFF_A  (OFF_BL + 38912)        // 78336; 2 bufs x 38912 (hi 19456 + lo 19456)
#define OFF_EPI (OFF_A + 77824)        // 156160
#define SMEM_G1 (OFF_EPI + 33792)      // 189952 B

// ---- gemm2 smem map (128-row tiles, ROWB2=272, K=128, single A buffer) ----
#define ROWB2 272
#define O2_BH 512
#define O2_BL (O2_BH + 34816)
#define O2_A  (O2_BL + 34816)          // 70144; single buf: hi 34816 + lo 34816
#define O2_EPI (O2_A + 69632)          // 139776; 64x132 floats
#define SMEM_G2 (O2_EPI + 33792)       // 173568 B

// ---------------- K0: segment bounds (batch sorted) ----------------
__global__ void k_bounds(const int* __restrict__ batch, int N) {
    int g = blockIdx.x * blockDim.x + threadIdx.x;
    if (g > NG) return;
    int lo = 0, hi = N;
    while (lo < hi) {
        int mid = (lo + hi) >> 1;
        if (batch[mid] < g) lo = mid + 1; else hi = mid;
    }
    g_seg[g] = lo;
}

// ---------------- K1: per-graph col means of x0 + lam1 = xm @ l1w^T ----------------
__global__ void k_lam1(const float* __restrict__ x, const float* __restrict__ pers0,
                       const float* __restrict__ l1w, int N) {
    __shared__ float s_sum[2][144];
    __shared__ float s_xm[144];
    int g  = blockIdx.x;
    int lo = g_seg[g], hi = g_seg[g + 1];
    int t  = threadIdx.x;
    int phase = t / 144, col = t - phase * 144;

    float acc = 0.f;
    if (col < 128) {
        const float* p = x + col;
        for (int r = lo + phase; r < hi; r += 2) acc += p[(size_t)r * 128];
    } else {
        int j = col - 128;
        int pp = j >> 1, c = j & 1;
        const float* p = pers0 + (size_t)pp * 2 * N + c;
        for (int r = lo + phase; r < hi; r += 2) acc += p[2 * (size_t)r];
    }
    s_sum[phase][col] = acc;
    __syncthreads();
    if (t < 144) {
        float cnt = (float)max(hi - lo, 1);
        s_xm[t] = (s_sum[0][t] + s_sum[1][t]) / cnt;
    }
    __syncthreads();
    if (t < 128) {
        const float* w = l1w + t * 144;
        float a = 0.f;
#pragma unroll 8
        for (int k = 0; k < 144; ++k) a += s_xm[k] * w[k];
        g_lam1[g * 128 + t] = a;
    }
}

// =============== K2: mma.sync GEMM1 (512 thr): h = relu(x0 @ g1w^T + g1b - lam1[g]) ===============
// 64-row tiles, 16 warps as 2M x 8N (warp: 32 rows x 16 cols). K=144 = 9 k16 steps.
__global__ __launch_bounds__(512, 1) void k_gemm1(
    const float* __restrict__ x, const float* __restrict__ pers0,
    const float* __restrict__ g1w, const float* __restrict__ g1b,
    const float* __restrict__ l2w, int N) {
    extern __shared__ char sm[];
    uint32_t su = smaddr(sm);
    float* sbias = (float*)sm;
    int g  = blockIdx.x;
    int lo = g_seg[g], hi = g_seg[g + 1];
    int tid = threadIdx.x;
    int wid = tid >> 5, l = tid & 31;
    int wm = wid & 1, wn = wid >> 1;           // 2M x 8N
    int seg = l >> 3, l7 = l & 7, gg = l >> 2, tg = l & 3;

    // stage B = g1w as bf16 hi/lo, row stride 304B
    for (int it = 0; it < 9; ++it) {
        int idx = tid + it * 512;            // [0, 128*36)
        int jr = idx / 36, k4 = idx - jr * 36;
        float4 v = ((const float4*)g1w)[idx];
        uint32_t h01, l01, h23, l23;
        bsplit2(v.x, v.y, h01, l01);
        bsplit2(v.z, v.w, h23, l23);
        int off = jr * ROWB + k4 * 8;
        *(uint2*)(sm + OFF_BH + off) = make_uint2(h01, h23);
        *(uint2*)(sm + OFF_BL + off) = make_uint2(l01, l23);
    }
    if (tid < 128) sbias[tid] = g1b[tid] - g_lam1[g * 128 + tid];

    // register prefetch of one 64-row x0 tile (row = tid>>3, k-eighth = tid&7)
    float4 xv[4]; float2 pv;
    int prow = tid >> 3, pk8 = tid & 7;
    auto loadRegs = [&](int r0i, int rem) {
        int rg = r0i + min(prow, rem - 1);
        const float4* xs = (const float4*)(x + (size_t)rg * 128) + pk8 * 4;
#pragma unroll
        for (int i = 0; i < 4; ++i) xv[i] = xs[i];
        pv = ((const float2*)pers0)[(size_t)pk8 * N + rg];
    };
    auto stsRegs = [&](int buf) {
        char* bh = sm + OFF_A + buf * 38912 + prow * ROWB;
        char* bl = bh + 19456;
#pragma unroll
        for (int i = 0; i < 4; ++i) {
            uint32_t h01, l01, h23, l23;
            bsplit2(xv[i].x, xv[i].y, h01, l01);
            bsplit2(xv[i].z, xv[i].w, h23, l23);
            *(uint2*)(bh + pk8 * 32 + i * 8) = make_uint2(h01, h23);
            *(uint2*)(bl + pk8 * 32 + i * 8) = make_uint2(l01, l23);
        }
        uint32_t h, lw;
        bsplit2(pv.x, pv.y, h, lw);
        *(uint32_t*)(bh + 256 + 4 * pk8) = h;
        *(uint32_t*)(bl + 256 + 4 * pk8) = lw;
    };

    float hs[16];
#pragma unroll
    for (int i = 0; i < 16; ++i) hs[i] = 0.f;

    uint32_t a_off = su + OFF_A  + (uint32_t)((wm * 32 + (seg & 1) * 8 + l7) * ROWB + (seg >> 1) * 16);
    uint32_t b_off = su + OFF_BH + (uint32_t)((wn * 16 + (seg >> 1) * 8 + l7) * ROWB + (seg & 1) * 16);

    if (lo < hi) { loadRegs(lo, min(64, hi - lo)); stsRegs(0); }
    __syncthreads();

    int t = 0;
    for (int r0 = lo; r0 < hi; r0 += 64, ++t) {
        int buf = t & 1;
        int nr0 = r0 + 64;
        bool havnext = nr0 < hi;
        if (havnext) loadRegs(nr0, min(64, hi - nr0));

        float D[4][4];
#pragma unroll
        for (int i = 0; i < 4; ++i)
#pragma unroll
            for (int q = 0; q < 4; ++q) D[i][q] = 0.f;

        uint32_t abase = a_off + buf * 38912;
#pragma unroll
        for (int ks = 0; ks < 9; ++ks) {
            uint32_t ah[2][4], al[2][4], bh4[4], bl4[4];
            ldsm4(ah[0], abase + ks * 32);
            ldsm4(al[0], abase + 19456 + ks * 32);
            ldsm4(ah[1], abase + 16 * ROWB + ks * 32);
            ldsm4(al[1], abase + 16 * ROWB + 19456 + ks * 32);
            ldsm4(bh4, b_off + ks * 32);
            ldsm4(bl4, b_off + 38912 + ks * 32);
#pragma unroll
            for (int m = 0; m < 2; ++m) {
                float* d0 = D[m * 2];
                float* d1 = D[m * 2 + 1];
                mma_bf16(d0, ah[m], bh4);
                mma_bf16(d1, ah[m], bh4 + 2);
                mma_bf16(d0, ah[m], bl4);
                mma_bf16(d1, ah[m], bl4 + 2);
                mma_bf16(d0, al[m], bh4);
                mma_bf16(d1, al[m], bh4 + 2);
            }
        }
        if (havnext) stsRegs(buf ^ 1);

        // single-phase epilogue: all 64 rows
        float* epi = (float*)(sm + OFF_EPI);
#pragma unroll
        for (int m = 0; m < 2; ++m)
#pragma unroll
        for (int h = 0; h < 2; ++h) {
            int d = m * 2 + h;
            int er = wm * 32 + m * 16 + gg;
            int c = wn * 16 + h * 8 + 2 * tg;
            *(float2*)(epi + er * 132 + c)       = make_float2(D[d][0], D[d][1]);
            *(float2*)(epi + (er + 8) * 132 + c) = make_float2(D[d][2], D[d][3]);
        }
        __syncthreads();
        {
            int r = tid >> 3, c0 = (tid & 7) * 16;
            int grow = r0 + r;
            if (grow < hi) {
                float v[16];
#pragma unroll
                for (int q = 0; q < 4; ++q)
                    *(float4*)(v + 4 * q) = *(const float4*)(epi + r * 132 + c0 + 4 * q);
                uint32_t hh[8], ll[8];
#pragma unroll
                for (int i = 0; i < 16; i += 2) {
                    float va = fmaxf(v[i]     + sbias[c0 + i],     0.f);
                    float vb = fmaxf(v[i + 1] + sbias[c0 + i + 1], 0.f);
                    hs[i] += va; hs[i + 1] += vb;
                    bsplit2(va, vb, hh[i >> 1], ll[i >> 1]);
                }
                size_t off = (size_t)grow * 128 + c0;
                *(uint4*)(g_hhi + off)     = make_uint4(hh[0], hh[1], hh[2], hh[3]);
                *(uint4*)(g_hhi + off + 8) = make_uint4(hh[4], hh[5], hh[6], hh[7]);
                *(uint4*)(g_hlo + off)     = make_uint4(ll[0], ll[1], ll[2], ll[3]);
                *(uint4*)(g_hlo + off + 8) = make_uint4(ll[4], ll[5], ll[6], ll[7]);
            }
        }
        __syncthreads();
    }

    // deterministic col-sum reduce -> hm -> lam2 = hm @ l2w^T
    float* red = (float*)(sm + OFF_EPI);
    __syncthreads();
#pragma unroll
    for (int i = 0; i < 16; ++i) red[tid * 16 + i] = hs[i];
    __syncthreads();
    if (tid < 128) {
        int o = tid >> 4, i = tid & 15;
        float s = 0.f;
        for (int ss = 0; ss < 64; ++ss) s += red[(ss * 8 + o) * 16 + i];
        float cnt = (float)max(hi - lo, 1);
        red[8192 + o * 16 + i] = s / cnt;
    }
    __syncthreads();
    if (tid < 128) {
        const float* w = l2w + tid * 128;
        const float* hm = red + 8192;
        float a = 0.f;
#pragma unroll 8
        for (int k = 0; k < 128; ++k) a += hm[k] * w[k];
        g_lam2[g * 128 + tid] = a;
    }
}

// =============== K4: mma.sync GEMM2 (512 thr): y0 = h @ g2w^T + g2b - lam2[g]; BN partials ===============
// 128-row tiles, 16 warps as 4M x 4N (warp: 32 rows x 32 cols). K=128 = 8 k16 steps.
// Single A buffer; next-tile cp.async issued after k-loop, overlapped with epilogue.
__global__ __launch_bounds__(512, 1) void k_gemm2(
    const float* __restrict__ g2w, const float* __restrict__ g2b, int N) {
    extern __shared__ char sm[];
    uint32_t su = smaddr(sm);
    float* sbias = (float*)sm;
    int g  = blockIdx.x;
    int lo = g_seg[g], hi = g_seg[g + 1];
    int tid = threadIdx.x;
    int wid = tid >> 5, l = tid & 31;
    int wm = wid & 3, wn = wid >> 2;           // 4M x 4N
    int seg = l >> 3, l7 = l & 7, gg = l >> 2, tg = l & 3;

    // stage B = g2w bf16 hi/lo (K=128), row stride 272B
    for (int it = 0; it < 8; ++it) {
        int idx = tid + it * 512;            // [0, 128*32)
        int jr = idx >> 5, k4 = idx & 31;
        float4 v = ((const float4*)g2w)[idx];
        uint32_t h01, l01, h23, l23;
        bsplit2(v.x, v.y, h01, l01);
        bsplit2(v.z, v.w, h23, l23);
        int off = jr * ROWB2 + k4 * 8;
        *(uint2*)(sm + O2_BH + off) = make_uint2(h01, h23);
        *(uint2*)(sm + O2_BL + off) = make_uint2(l01, l23);
    }
    if (tid < 128) sbias[tid] = g2b[tid] - g_lam2[g * 128 + tid];

    // A staging via cp.async from pre-split h arrays (128 rows per tile, single buffer)
    auto stageA = [&](int r0i, int rem) {
#pragma unroll
        for (int hl = 0; hl < 2; ++hl) {
            const __nv_bfloat16* src = hl ? g_hlo : g_hhi;
            uint32_t base = su + O2_A + hl * 34816;
#pragma unroll
            for (int it = 0; it < 4; ++it) {
                int idx = tid + it * 512;        // [0, 128*16)
                int r = idx >> 4, u = idx & 15;
                int rc = (r < rem) ? r : 0;
                cp16(base + r * ROWB2 + u * 16,
                     src + (size_t)(r0i + rc) * 128 + u * 8, (r < rem) ? 16 : 0);
            }
        }
    };

    float ssum[16], ssq[16];
#pragma unroll
    for (int i = 0; i < 16; ++i) { ssum[i] = 0.f; ssq[i] = 0.f; }

    uint32_t a_off = su + O2_A  + (uint32_t)((wm * 32 + (seg & 1) * 8 + l7) * ROWB2 + (seg >> 1) * 16);
    uint32_t b_off = su + O2_BH + (uint32_t)((wn * 32 + (seg >> 1) * 8 + l7) * ROWB2 + (seg & 1) * 16);

    if (lo < hi) { stageA(lo, min(128, hi - lo)); CP_COMMIT(); }
    CP_WAIT0();
    __syncthreads();

    for (int r0 = lo; r0 < hi; r0 += 128) {
        int nr0 = r0 + 128;
        bool havnext = nr0 < hi;

        float D[8][4];
#pragma unroll
        for (int i = 0; i < 8; ++i)
#pragma unroll
            for (int q = 0; q < 4; ++q) D[i][q] = 0.f;

#pragma unroll
        for (int ks = 0; ks < 8; ++ks) {
            uint32_t ah[2][4], al[2][4], bh4[2][4], bl4[2][4];
#pragma unroll
            for (int m = 0; m < 2; ++m) {
                ldsm4(ah[m], a_off + m * (16 * ROWB2) + ks * 32);
                ldsm4(al[m], a_off + m * (16 * ROWB2) + 34816 + ks * 32);
            }
#pragma unroll
            for (int nt = 0; nt < 2; ++nt) {
                ldsm4(bh4[nt], b_off + nt * (16 * ROWB2) + ks * 32);
                ldsm4(bl4[nt], b_off + nt * (16 * ROWB2) + 34816 + ks * 32);
            }
#pragma unroll
            for (int m = 0; m < 2; ++m)
#pragma unroll
            for (int nt = 0; nt < 2; ++nt) {
                float* d0 = D[m * 4 + nt * 2];
                float* d1 = D[m * 4 + nt * 2 + 1];
                mma_bf16(d0, ah[m], bh4[nt]);
                mma_bf16(d1, ah[m], bh4[nt] + 2);
                mma_bf16(d0, ah[m], bl4[nt]);
                mma_bf16(d1, ah[m], bl4[nt] + 2);
                mma_bf16(d0, al[m], bh4[nt]);
                mma_bf16(d1, al[m], bh4[nt] + 2);
            }
        }

        __syncthreads();   // all warps done reading A buffer
        if (havnext) { stageA(nr0, min(128, hi - nr0)); CP_COMMIT(); }  // overlaps epilogue

        // epilogue: 2 phases of 64 rows through smem
        float* epi = (float*)(sm + O2_EPI);
#pragma unroll
        for (int p = 0; p < 2; ++p) {
            if ((wm >> 1) == p) {
#pragma unroll
                for (int m = 0; m < 2; ++m)
#pragma unroll
                for (int nt = 0; nt < 2; ++nt)
#pragma unroll
                for (int h = 0; h < 2; ++h) {
                    int d = m * 4 + nt * 2 + h;
                    int er = (wm & 1) * 32 + m * 16 + gg;
                    int c = wn * 32 + nt * 16 + h * 8 + 2 * tg;
                    *(float2*)(epi + er * 132 + c)       = make_float2(D[d][0], D[d][1]);
                    *(float2*)(epi + (er + 8) * 132 + c) = make_float2(D[d][2], D[d][3]);
                }
            }
            __syncthreads();
            int r = tid >> 3, c0 = (tid & 7) * 16;
            int grow = r0 + p * 64 + r;
            if (grow < hi) {
                float v[16];
#pragma unroll
                for (int q = 0; q < 4; ++q)
                    *(float4*)(v + 4 * q) = *(const float4*)(epi + r * 132 + c0 + 4 * q);
#pragma unroll
                for (int i = 0; i < 16; ++i) {
                    float vv = v[i] + sbias[c0 + i];
                    v[i] = vv;
                    ssum[i] += vv;
                    ssq[i]  += vv * vv;
                }
                float* dst = g_y + (size_t)grow * 128 + c0;
#pragma unroll
                for (int q = 0; q < 4; ++q) *(float4*)(dst + 4 * q) = *(float4*)(v + 4 * q);
            }
            __syncthreads();
        }
        if (havnext) CP_WAIT0();
        __syncthreads();
    }

    // deterministic BN partials
    float* red = (float*)(sm + O2_EPI);
    __syncthreads();
#pragma unroll
    for (int i = 0; i < 16; ++i) red[tid * 16 + i] = ssum[i];
    __syncthreads();
    if (tid < 128) {
        int o = tid >> 4, i = tid & 15;
        float s = 0.f;
        for (int ss = 0; ss < 64; ++ss) s += red[(ss * 8 + o) * 16 + i];
        g_psum[g * 128 + o * 16 + i] = s;
    }
    __syncthreads();
#pragma unroll
    for (int i = 0; i < 16; ++i) red[tid * 16 + i] = ssq[i];
    __syncthreads();
    if (tid < 128) {
        int o = tid >> 4, i = tid & 15;
        float s = 0.f;
        for (int ss = 0; ss < 64; ++ss) s += red[(ss * 8 + o) * 16 + i];
        g_psq[g * 128 + o * 16 + i] = s;
    }
}

// ---------------- K5: BN stats -> scale/shift ----------------
__global__ void k_stats(const float* __restrict__ bn_g, const float* __restrict__ bn_b, int N) {
    int t = threadIdx.x;  // 128
    float s = 0.f, q = 0.f;
    for (int g = 0; g < NG; ++g) {
        s += g_psum[g * 128 + t];
        q += g_psq[g * 128 + t];
    }
    float invN = 1.f / (float)N;
    float mu  = s * invN;
    float var = fmaxf(q * invN - mu * mu, 0.f);
    float sc  = rsqrtf(var + BN_EPS) * bn_g[t];
    g_scale[t] = sc;
    g_shift[t] = bn_b[t] - mu * sc;
}

// ---------------- K6: out = x + y0*scale + shift ----------------
__global__ void k_out(const float* __restrict__ x, float* __restrict__ out, int total4) {
    int i = blockIdx.x * blockDim.x + threadIdx.x;
    if (i >= total4) return;
    int j4 = i & 31;
    float4 sc = ((const float4*)g_scale)[j4];
    float4 sh = ((const float4*)g_shift)[j4];
    float4 xv = ((const float4*)x)[i];
    float4 yv = ((const float4*)g_y)[i];
    float4 o;
    o.x = xv.x + yv.x * sc.x + sh.x;
    o.y = xv.y + yv.y * sc.y + sh.y;
    o.z = xv.z + yv.z * sc.z + sh.z;
    o.w = xv.w + yv.w * sc.w + sh.w;
    ((float4*)out)[i] = o;
}

// ---------------- launch ----------------
extern "C" void kernel_launch(void* const* d_in, const int* in_sizes, int n_in,
                              void* d_out, int out_size) {
    const float* x     = (const float*)d_in[0];
    const int*   batch = (const int*)d_in[1];
    const float* pers0 = (const float*)d_in[2];
    const float* g1w   = (const float*)d_in[3];
    const float* g1b   = (const float*)d_in[4];
    const float* l1w   = (const float*)d_in[5];
    const float* g2w   = (const float*)d_in[6];
    const float* g2b   = (const float*)d_in[7];
    const float* l2w   = (const float*)d_in[8];
    const float* bng   = (const float*)d_in[9];
    const float* bnb   = (const float*)d_in[10];
    float* out = (float*)d_out;
    int N = in_sizes[0] / 128;

    cudaFuncSetAttribute(k_gemm1, cudaFuncAttributeMaxDynamicSharedMemorySize, SMEM_G1);
    cudaFuncSetAttribute(k_gemm2, cudaFuncAttributeMaxDynamicSharedMemorySize, SMEM_G2);

    k_bounds<<<(NG + 256) / 256, 256>>>(batch, N);
    k_lam1<<<NG, 288>>>(x, pers0, l1w, N);
    k_gemm1<<<NG, 512, SMEM_G1>>>(x, pers0, g1w, g1b, l2w, N);
    k_gemm2<<<NG, 512, SMEM_G2>>>(g2w, g2b, N);
    k_stats<<<1, 128>>>(bng, bnb, N);
    int total4 = N * 32;
    k_out<<<(total4 + 255) / 256, 256>>>(x, out, total4);
}

// round 13
// speedup vs baseline: 1.0427x; 1.0427x over previous
#include <cuda_runtime.h>
#include <cuda_bf16.h>
#include <cstdint>

#define NG   2048
#define MAXN 500000
#define BN_EPS 1e-5f

typedef unsigned long long ull;

// ---------------- scratch (device globals; no allocation allowed) ----------------
__device__ __align__(16) __nv_bfloat16 g_hhi[(size_t)MAXN * 128];
__device__ __align__(16) __nv_bfloat16 g_hlo[(size_t)MAXN * 128];
__device__ __align__(16) float g_y[(size_t)MAXN * 128];
__device__ __align__(16) float g_lam1[NG * 128];
__device__ __align__(16) float g_lam2[NG * 128];
__device__ __align__(16) float g_psum[NG * 128];
__device__ __align__(16) float g_psq[NG * 128];
__device__ __align__(16) float g_scale[128];
__device__ __align__(16) float g_shift[128];
__device__ int g_seg[NG + 1];

// ---------------- helpers ----------------
__device__ __forceinline__ uint32_t smaddr(const void* p) {
    return (uint32_t)__cvta_generic_to_shared(p);
}
__device__ __forceinline__ void cp16(uint32_t d, const void* s, int n) {
    asm volatile("cp.async.ca.shared.global [%0], [%1], 16, %2;\n" :: "r"(d), "l"(s), "r"(n));
}
#define CP_COMMIT() asm volatile("cp.async.commit_group;\n" ::: "memory")
#define CP_WAIT0()  asm volatile("cp.async.wait_group 0;\n" ::: "memory")

__device__ __forceinline__ void mma_bf16(float* d, const uint32_t* a, const uint32_t* b) {
    asm volatile(
        "mma.sync.aligned.m16n8k16.row.col.f32.bf16.bf16.f32 "
        "{%0,%1,%2,%3}, {%4,%5,%6,%7}, {%8,%9}, {%0,%1,%2,%3};"
        : "+f"(d[0]), "+f"(d[1]), "+f"(d[2]), "+f"(d[3])
        : "r"(a[0]), "r"(a[1]), "r"(a[2]), "r"(a[3]), "r"(b[0]), "r"(b[1]));
}
__device__ __forceinline__ void ldsm4(uint32_t* r, uint32_t a) {
    asm volatile("ldmatrix.sync.aligned.m8n8.x4.shared.b16 {%0,%1,%2,%3}, [%4];"
        : "=r"(r[0]), "=r"(r[1]), "=r"(r[2]), "=r"(r[3]) : "r"(a));
}

__device__ __forceinline__ void bsplit2(float a, float b, uint32_t& hi, uint32_t& lo) {
    __nv_bfloat162 h = __floats2bfloat162_rn(a, b);
    hi = *reinterpret_cast<uint32_t*>(&h);
    float ra = a - __bfloat162float(h.x);
    float rb = b - __bfloat162float(h.y);
    __nv_bfloat162 l = __floats2bfloat162_rn(ra, rb);
    lo = *reinterpret_cast<uint32_t*>(&l);
}

// ---- gemm1 smem map (64-row tiles, ROWB=304, K=144) ----
#define ROWB 304
#define OFF_BH 512
#define OFF_BL (OFF_BH + 38912)
#define OFF_A  (OFF_BL + 38912)        // 78336; 2 bufs x 38912 (hi 19456 + lo 19456)
#define OFF_EPI (OFF_A + 77824)        // 156160
#define SMEM_G1 (OFF_EPI + 33792)      // 189952 B

// ---- gemm2 smem map (64-row tiles, ROWB2=272, K=128, B held in registers) ----
// B staged once at 512 (hi 34816 + lo 34816), then region reused:
//   A bufs (2 x 34816: hi 17408 + lo 17408) at 512; epi at 512+69632
#define ROWB2 272
#define O2_A   512
#define O2_EPI (512 + 69632)           // 70144
#define SMEM_G2 (O2_EPI + 33792)       // 103936 B

// ---------------- K0: segment bounds (batch sorted) ----------------
__global__ void k_bounds(const int* __restrict__ batch, int N) {
    int g = blockIdx.x * blockDim.x + threadIdx.x;
    if (g > NG) return;
    int lo = 0, hi = N;
    while (lo < hi) {
        int mid = (lo + hi) >> 1;
        if (batch[mid] < g) lo = mid + 1; else hi = mid;
    }
    g_seg[g] = lo;
}

// ---------------- K1: per-graph col means of x0 + lam1 = xm @ l1w^T ----------------
__global__ void k_lam1(const float* __restrict__ x, const float* __restrict__ pers0,
                       const float* __restrict__ l1w, int N) {
    __shared__ float s_sum[2][144];
    __shared__ float s_xm[144];
    int g  = blockIdx.x;
    int lo = g_seg[g], hi = g_seg[g + 1];
    int t  = threadIdx.x;
    int phase = t / 144, col = t - phase * 144;

    float acc = 0.f;
    if (col < 128) {
        const float* p = x + col;
        for (int r = lo + phase; r < hi; r += 2) acc += p[(size_t)r * 128];
    } else {
        int j = col - 128;
        int pp = j >> 1, c = j & 1;
        const float* p = pers0 + (size_t)pp * 2 * N + c;
        for (int r = lo + phase; r < hi; r += 2) acc += p[2 * (size_t)r];
    }
    s_sum[phase][col] = acc;
    __syncthreads();
    if (t < 144) {
        float cnt = (float)max(hi - lo, 1);
        s_xm[t] = (s_sum[0][t] + s_sum[1][t]) / cnt;
    }
    __syncthreads();
    if (t < 128) {
        const float* w = l1w + t * 144;
        float a = 0.f;
#pragma unroll 8
        for (int k = 0; k < 144; ++k) a += s_xm[k] * w[k];
        g_lam1[g * 128 + t] = a;
    }
}

// =============== K2: mma.sync GEMM1 (512 thr): h = relu(x0 @ g1w^T + g1b - lam1[g]) ===============
// 64-row tiles, 16 warps as 2M x 8N (warp: 32 rows x 16 cols). K=144 = 9 k16 steps.
__global__ __launch_bounds__(512, 1) void k_gemm1(
    const float* __restrict__ x, const float* __restrict__ pers0,
    const float* __restrict__ g1w, const float* __restrict__ g1b,
    const float* __restrict__ l2w, int N) {
    extern __shared__ char sm[];
    uint32_t su = smaddr(sm);
    float* sbias = (float*)sm;
    int g  = blockIdx.x;
    int lo = g_seg[g], hi = g_seg[g + 1];
    int tid = threadIdx.x;
    int wid = tid >> 5, l = tid & 31;
    int wm = wid & 1, wn = wid >> 1;           // 2M x 8N
    int seg = l >> 3, l7 = l & 7, gg = l >> 2, tg = l & 3;

    // stage B = g1w as bf16 hi/lo, row stride 304B
    for (int it = 0; it < 9; ++it) {
        int idx = tid + it * 512;            // [0, 128*36)
        int jr = idx / 36, k4 = idx - jr * 36;
        float4 v = ((const float4*)g1w)[idx];
        uint32_t h01, l01, h23, l23;
        bsplit2(v.x, v.y, h01, l01);
        bsplit2(v.z, v.w, h23, l23);
        int off = jr * ROWB + k4 * 8;
        *(uint2*)(sm + OFF_BH + off) = make_uint2(h01, h23);
        *(uint2*)(sm + OFF_BL + off) = make_uint2(l01, l23);
    }
    if (tid < 128) sbias[tid] = g1b[tid] - g_lam1[g * 128 + tid];

    // register prefetch of one 64-row x0 tile (row = tid>>3, k-eighth = tid&7)
    float4 xv[4]; float2 pv;
    int prow = tid >> 3, pk8 = tid & 7;
    auto loadRegs = [&](int r0i, int rem) {
        int rg = r0i + min(prow, rem - 1);
        const float4* xs = (const float4*)(x + (size_t)rg * 128) + pk8 * 4;
#pragma unroll
        for (int i = 0; i < 4; ++i) xv[i] = xs[i];
        pv = ((const float2*)pers0)[(size_t)pk8 * N + rg];
    };
    auto stsRegs = [&](int buf) {
        char* bh = sm + OFF_A + buf * 38912 + prow * ROWB;
        char* bl = bh + 19456;
#pragma unroll
        for (int i = 0; i < 4; ++i) {
            uint32_t h01, l01, h23, l23;
            bsplit2(xv[i].x, xv[i].y, h01, l01);
            bsplit2(xv[i].z, xv[i].w, h23, l23);
            *(uint2*)(bh + pk8 * 32 + i * 8) = make_uint2(h01, h23);
            *(uint2*)(bl + pk8 * 32 + i * 8) = make_uint2(l01, l23);
        }
        uint32_t h, lw;
        bsplit2(pv.x, pv.y, h, lw);
        *(uint32_t*)(bh + 256 + 4 * pk8) = h;
        *(uint32_t*)(bl + 256 + 4 * pk8) = lw;
    };

    float hs[16];
#pragma unroll
    for (int i = 0; i < 16; ++i) hs[i] = 0.f;

    uint32_t a_off = su + OFF_A  + (uint32_t)((wm * 32 + (seg & 1) * 8 + l7) * ROWB + (seg >> 1) * 16);
    uint32_t b_off = su + OFF_BH + (uint32_t)((wn * 16 + (seg >> 1) * 8 + l7) * ROWB + (seg & 1) * 16);

    if (lo < hi) { loadRegs(lo, min(64, hi - lo)); stsRegs(0); }
    __syncthreads();

    int t = 0;
    for (int r0 = lo; r0 < hi; r0 += 64, ++t) {
        int buf = t & 1;
        int nr0 = r0 + 64;
        bool havnext = nr0 < hi;
        if (havnext) loadRegs(nr0, min(64, hi - nr0));

        float D[4][4];
#pragma unroll
        for (int i = 0; i < 4; ++i)
#pragma unroll
            for (int q = 0; q < 4; ++q) D[i][q] = 0.f;

        uint32_t abase = a_off + buf * 38912;
#pragma unroll
        for (int ks = 0; ks < 9; ++ks) {
            uint32_t ah[2][4], al[2][4], bh4[4], bl4[4];
            ldsm4(ah[0], abase + ks * 32);
            ldsm4(al[0], abase + 19456 + ks * 32);
            ldsm4(ah[1], abase + 16 * ROWB + ks * 32);
            ldsm4(al[1], abase + 16 * ROWB + 19456 + ks * 32);
            ldsm4(bh4, b_off + ks * 32);
            ldsm4(bl4, b_off + 38912 + ks * 32);
#pragma unroll
            for (int m = 0; m < 2; ++m) {
                float* d0 = D[m * 2];
                float* d1 = D[m * 2 + 1];
                mma_bf16(d0, ah[m], bh4);
                mma_bf16(d1, ah[m], bh4 + 2);
                mma_bf16(d0, ah[m], bl4);
                mma_bf16(d1, ah[m], bl4 + 2);
                mma_bf16(d0, al[m], bh4);
                mma_bf16(d1, al[m], bh4 + 2);
            }
        }
        if (havnext) stsRegs(buf ^ 1);

        // single-phase epilogue: all 64 rows
        float* epi = (float*)(sm + OFF_EPI);
#pragma unroll
        for (int m = 0; m < 2; ++m)
#pragma unroll
        for (int h = 0; h < 2; ++h) {
            int d = m * 2 + h;
            int er = wm * 32 + m * 16 + gg;
            int c = wn * 16 + h * 8 + 2 * tg;
            *(float2*)(epi + er * 132 + c)       = make_float2(D[d][0], D[d][1]);
            *(float2*)(epi + (er + 8) * 132 + c) = make_float2(D[d][2], D[d][3]);
        }
        __syncthreads();
        {
            int r = tid >> 3, c0 = (tid & 7) * 16;
            int grow = r0 + r;
            if (grow < hi) {
                float v[16];
#pragma unroll
                for (int q = 0; q < 4; ++q)
                    *(float4*)(v + 4 * q) = *(const float4*)(epi + r * 132 + c0 + 4 * q);
                uint32_t hh[8], ll[8];
#pragma unroll
                for (int i = 0; i < 16; i += 2) {
                    float va = fmaxf(v[i]     + sbias[c0 + i],     0.f);
                    float vb = fmaxf(v[i + 1] + sbias[c0 + i + 1], 0.f);
                    hs[i] += va; hs[i + 1] += vb;
                    bsplit2(va, vb, hh[i >> 1], ll[i >> 1]);
                }
                size_t off = (size_t)grow * 128 + c0;
                *(uint4*)(g_hhi + off)     = make_uint4(hh[0], hh[1], hh[2], hh[3]);
                *(uint4*)(g_hhi + off + 8) = make_uint4(hh[4], hh[5], hh[6], hh[7]);
                *(uint4*)(g_hlo + off)     = make_uint4(ll[0], ll[1], ll[2], ll[3]);
                *(uint4*)(g_hlo + off + 8) = make_uint4(ll[4], ll[5], ll[6], ll[7]);
            }
        }
        __syncthreads();
    }

    // deterministic col-sum reduce -> hm -> lam2 = hm @ l2w^T
    float* red = (float*)(sm + OFF_EPI);
    __syncthreads();
#pragma unroll
    for (int i = 0; i < 16; ++i) red[tid * 16 + i] = hs[i];
    __syncthreads();
    if (tid < 128) {
        int o = tid >> 4, i = tid & 15;
        float s = 0.f;
        for (int ss = 0; ss < 64; ++ss) s += red[(ss * 8 + o) * 16 + i];
        float cnt = (float)max(hi - lo, 1);
        red[8192 + o * 16 + i] = s / cnt;
    }
    __syncthreads();
    if (tid < 128) {
        const float* w = l2w + tid * 128;
        const float* hm = red + 8192;
        float a = 0.f;
#pragma unroll 8
        for (int k = 0; k < 128; ++k) a += hm[k] * w[k];
        g_lam2[g * 128 + tid] = a;
    }
}

// =============== K4: mma.sync GEMM2 (512 thr): y0 = h @ g2w^T + g2b - lam2[g]; BN partials ===============
// 64-row tiles, 16 warps as 2M x 8N (warp: 32 rows x 16 cols). K=128 = 8 k16 steps.
// B (weights) fragments resident in REGISTERS for the whole kernel (loaded once).
// BN sums decomposed: accumulate raw D / D^2, bias fixed up analytically at the end.
__global__ __launch_bounds__(512, 1) void k_gemm2(
    const float* __restrict__ g2w, const float* __restrict__ g2b, int N) {
    extern __shared__ char sm[];
    uint32_t su = smaddr(sm);
    float* sbias = (float*)sm;
    int g  = blockIdx.x;
    int lo = g_seg[g], hi = g_seg[g + 1];
    int tid = threadIdx.x;
    int wid = tid >> 5, l = tid & 31;
    int wm = wid & 1, wn = wid >> 1;           // 2M x 8N
    int seg = l >> 3, l7 = l & 7, gg = l >> 2, tg = l & 3;

    // stage B = g2w bf16 hi/lo into smem once (hi at 512, lo at 512+34816)
    for (int it = 0; it < 8; ++it) {
        int idx = tid + it * 512;            // [0, 128*32)
        int jr = idx >> 5, k4 = idx & 31;
        float4 v = ((const float4*)g2w)[idx];
        uint32_t h01, l01, h23, l23;
        bsplit2(v.x, v.y, h01, l01);
        bsplit2(v.z, v.w, h23, l23);
        int off = jr * ROWB2 + k4 * 8;
        *(uint2*)(sm + 512 + off)         = make_uint2(h01, h23);
        *(uint2*)(sm + 512 + 34816 + off) = make_uint2(l01, l23);
    }
    if (tid < 128) sbias[tid] = g2b[tid] - g_lam2[g * 128 + tid];
    __syncthreads();

    // load B fragments to registers: per warp 16 cols x K=128, hi+lo = 64 regs
    uint32_t bh[8][4], bl[8][4];
    {
        uint32_t b_off = su + 512 + (uint32_t)((wn * 16 + (seg >> 1) * 8 + l7) * ROWB2 + (seg & 1) * 16);
#pragma unroll
        for (int ks = 0; ks < 8; ++ks) {
            ldsm4(bh[ks], b_off + ks * 32);
            ldsm4(bl[ks], b_off + 34816 + ks * 32);
        }
    }
    __syncthreads();   // B smem dead; region now reused for A buffers

    // A staging via cp.async from pre-split h arrays (64 rows per tile)
    auto stageA = [&](int r0i, int rem, int buf) {
#pragma unroll
        for (int hl = 0; hl < 2; ++hl) {
            const __nv_bfloat16* src = hl ? g_hlo : g_hhi;
            uint32_t base = su + O2_A + buf * 34816 + hl * 17408;
#pragma unroll
            for (int it = 0; it < 2; ++it) {
                int idx = tid + it * 512;        // [0, 64*16)
                int r = idx >> 4, u = idx & 15;
                int rc = (r < rem) ? r : 0;
                cp16(base + r * ROWB2 + u * 16,
                     src + (size_t)(r0i + rc) * 128 + u * 8, (r < rem) ? 16 : 0);
            }
        }
    };

    float sD[4] = {0.f, 0.f, 0.f, 0.f}, sQ[4] = {0.f, 0.f, 0.f, 0.f};

    uint32_t a_off = su + O2_A + (uint32_t)((wm * 32 + (seg & 1) * 8 + l7) * ROWB2 + (seg >> 1) * 16);

    if (lo < hi) { stageA(lo, min(64, hi - lo), 0); CP_COMMIT(); CP_WAIT0(); }
    __syncthreads();

    int t = 0;
    for (int r0 = lo; r0 < hi; r0 += 64, ++t) {
        int buf = t & 1;
        int nr0 = r0 + 64;
        bool havnext = nr0 < hi;
        if (havnext) { stageA(nr0, min(64, hi - nr0), buf ^ 1); CP_COMMIT(); }

        float D[4][4];
#pragma unroll
        for (int i = 0; i < 4; ++i)
#pragma unroll
            for (int q = 0; q < 4; ++q) D[i][q] = 0.f;

        uint32_t abase = a_off + buf * 34816;
#pragma unroll
        for (int ks = 0; ks < 8; ++ks) {
            uint32_t ah0[4], al0[4], ah1[4], al1[4];
            ldsm4(ah0, abase + ks * 32);
            ldsm4(al0, abase + 17408 + ks * 32);
            ldsm4(ah1, abase + 16 * ROWB2 + ks * 32);
            ldsm4(al1, abase + 16 * ROWB2 + 17408 + ks * 32);
            mma_bf16(D[0], ah0, bh[ks]);     mma_bf16(D[1], ah0, bh[ks] + 2);
            mma_bf16(D[0], ah0, bl[ks]);     mma_bf16(D[1], ah0, bl[ks] + 2);
            mma_bf16(D[0], al0, bh[ks]);     mma_bf16(D[1], al0, bh[ks] + 2);
            mma_bf16(D[2], ah1, bh[ks]);     mma_bf16(D[3], ah1, bh[ks] + 2);
            mma_bf16(D[2], ah1, bl[ks]);     mma_bf16(D[3], ah1, bl[ks] + 2);
            mma_bf16(D[2], al1, bh[ks]);     mma_bf16(D[3], al1, bh[ks] + 2);
        }

        // accumulate raw sums (pre-bias) with row-validity masks
#pragma unroll
        for (int m = 0; m < 2; ++m) {
            int rA = r0 + wm * 32 + m * 16 + gg;
            bool v0 = rA < hi, v1 = (rA + 8) < hi;
#pragma unroll
            for (int h = 0; h < 2; ++h) {
                float* d = D[m * 2 + h];
                if (v0) {
                    sD[h * 2 + 0] += d[0]; sQ[h * 2 + 0] += d[0] * d[0];
                    sD[h * 2 + 1] += d[1]; sQ[h * 2 + 1] += d[1] * d[1];
                }
                if (v1) {
                    sD[h * 2 + 0] += d[2]; sQ[h * 2 + 0] += d[2] * d[2];
                    sD[h * 2 + 1] += d[3]; sQ[h * 2 + 1] += d[3] * d[3];
                }
            }
        }

        // epilogue: store y via smem roundtrip (bias applied by reading thread)
        float* epi = (float*)(sm + O2_EPI);
#pragma unroll
        for (int m = 0; m < 2; ++m)
#pragma unroll
        for (int h = 0; h < 2; ++h) {
            float* d = D[m * 2 + h];
            int er = wm * 32 + m * 16 + gg;
            int c = wn * 16 + h * 8 + 2 * tg;
            *(float2*)(epi + er * 132 + c)       = make_float2(d[0], d[1]);
            *(float2*)(epi + (er + 8) * 132 + c) = make_float2(d[2], d[3]);
        }
        __syncthreads();
        {
            int r = tid >> 3, c0 = (tid & 7) * 16;
            int grow = r0 + r;
            if (grow < hi) {
                float v[16];
#pragma unroll
                for (int q = 0; q < 4; ++q)
                    *(float4*)(v + 4 * q) = *(const float4*)(epi + r * 132 + c0 + 4 * q);
#pragma unroll
                for (int i = 0; i < 16; ++i) v[i] += sbias[c0 + i];
                float* dst = g_y + (size_t)grow * 128 + c0;
#pragma unroll
                for (int q = 0; q < 4; ++q) *(float4*)(dst + 4 * q) = *(float4*)(v + 4 * q);
            }
        }
        if (havnext) CP_WAIT0();
        __syncthreads();
    }

    // deterministic BN partials: fixed-order reduce of raw sums + analytic bias fixup
    float* red = (float*)(sm + O2_EPI);
    __syncthreads();
#pragma unroll
    for (int i = 0; i < 4; ++i) { red[tid * 8 + i] = sD[i]; red[tid * 8 + 4 + i] = sQ[i]; }
    __syncthreads();
    if (tid < 128) {
        int c = tid;
        int wn_ = c >> 4, cc = c & 15;
        int tg_ = (cc & 7) >> 1, par = cc & 1, s = (cc >> 3) * 2 + par;
        float sum = 0.f, sq = 0.f;
#pragma unroll
        for (int wm_ = 0; wm_ < 2; ++wm_)
            for (int gg_ = 0; gg_ < 8; ++gg_) {
                int tt = (wn_ * 2 + wm_) * 32 + gg_ * 4 + tg_;
                sum += red[tt * 8 + s];
                sq  += red[tt * 8 + 4 + s];
            }
        float b = sbias[c];
        float cnt = (float)(hi - lo);
        g_psum[g * 128 + c] = sum + cnt * b;
        g_psq[g * 128 + c]  = sq + 2.f * b * sum + cnt * b * b;
    }
}

// ---------------- K5: BN stats -> scale/shift ----------------
__global__ void k_stats(const float* __restrict__ bn_g, const float* __restrict__ bn_b, int N) {
    int t = threadIdx.x;  // 128
    float s = 0.f, q = 0.f;
    for (int g = 0; g < NG; ++g) {
        s += g_psum[g * 128 + t];
        q += g_psq[g * 128 + t];
    }
    float invN = 1.f / (float)N;
    float mu  = s * invN;
    float var = fmaxf(q * invN - mu * mu, 0.f);
    float sc  = rsqrtf(var + BN_EPS) * bn_g[t];
    g_scale[t] = sc;
    g_shift[t] = bn_b[t] - mu * sc;
}

// ---------------- K6: out = x + y0*scale + shift ----------------
__global__ void k_out(const float* __restrict__ x, float* __restrict__ out, int total4) {
    int i = blockIdx.x * blockDim.x + threadIdx.x;
    if (i >= total4) return;
    int j4 = i & 31;
    float4 sc = ((const float4*)g_scale)[j4];
    float4 sh = ((const float4*)g_shift)[j4];
    float4 xv = ((const float4*)x)[i];
    float4 yv = ((const float4*)g_y)[i];
    float4 o;
    o.x = xv.x + yv.x * sc.x + sh.x;
    o.y = xv.y + yv.y * sc.y + sh.y;
    o.z = xv.z + yv.z * sc.z + sh.z;
    o.w = xv.w + yv.w * sc.w + sh.w;
    ((float4*)out)[i] = o;
}

// ---------------- launch ----------------
extern "C" void kernel_launch(void* const* d_in, const int* in_sizes, int n_in,
                              void* d_out, int out_size) {
    const float* x     = (const float*)d_in[0];
    const int*   batch = (const int*)d_in[1];
    const float* pers0 = (const float*)d_in[2];
    const float* g1w   = (const float*)d_in[3];
    const float* g1b   = (const float*)d_in[4];
    const float* l1w   = (const float*)d_in[5];
    const float* g2w   = (const float*)d_in[6];
    const float* g2b   = (const float*)d_in[7];
    const float* l2w   = (const float*)d_in[8];
    const float* bng   = (const float*)d_in[9];
    const float* bnb   = (const float*)d_in[10];
    float* out = (float*)d_out;
    int N = in_sizes[0] / 128;

    cudaFuncSetAttribute(k_gemm1, cudaFuncAttributeMaxDynamicSharedMemorySize, SMEM_G1);
    cudaFuncSetAttribute(k_gemm2, cudaFuncAttributeMaxDynamicSharedMemorySize, SMEM_G2);

    k_bounds<<<(NG + 256) / 256, 256>>>(batch, N);
    k_lam1<<<NG, 288>>>(x, pers0, l1w, N);
    k_gemm1<<<NG, 512, SMEM_G1>>>(x, pers0, g1w, g1b, l2w, N);
    k_gemm2<<<NG, 512, SMEM_G2>>>(g2w, g2b, N);
    k_stats<<<1, 128>>>(bng, bnb, N);
    int total4 = N * 32;
    k_out<<<(total4 + 255) / 256, 256>>>(x, out, total4);
}

// round 14
// speedup vs baseline: 1.0729x; 1.0290x over previous
#include <cuda_runtime.h>
#include <cuda_bf16.h>
#include <cstdint>

#define NG   2048
#define MAXN 500000
#define BN_EPS 1e-5f

typedef unsigned long long ull;

// ---------------- scratch (device globals; no allocation allowed) ----------------
__device__ __align__(16) __nv_bfloat16 g_hhi[(size_t)MAXN * 128];
__device__ __align__(16) __nv_bfloat16 g_hlo[(size_t)MAXN * 128];
__device__ __align__(16) float g_y[(size_t)MAXN * 128];
__device__ __align__(16) float g_lam1[NG * 128];
__device__ __align__(16) float g_lam2[NG * 128];
__device__ __align__(16) float g_psum[NG * 128];
__device__ __align__(16) float g_psq[NG * 128];
__device__ __align__(16) float g_scale[128];
__device__ __align__(16) float g_shift[128];
__device__ int g_seg[NG + 1];

// ---------------- helpers ----------------
__device__ __forceinline__ uint32_t smaddr(const void* p) {
    return (uint32_t)__cvta_generic_to_shared(p);
}
__device__ __forceinline__ void cp16(uint32_t d, const void* s, int n) {
    asm volatile("cp.async.ca.shared.global [%0], [%1], 16, %2;\n" :: "r"(d), "l"(s), "r"(n));
}
#define CP_COMMIT() asm volatile("cp.async.commit_group;\n" ::: "memory")
#define CP_WAIT0()  asm volatile("cp.async.wait_group 0;\n" ::: "memory")

__device__ __forceinline__ void mma_bf16(float* d, const uint32_t* a, const uint32_t* b) {
    asm volatile(
        "mma.sync.aligned.m16n8k16.row.col.f32.bf16.bf16.f32 "
        "{%0,%1,%2,%3}, {%4,%5,%6,%7}, {%8,%9}, {%0,%1,%2,%3};"
        : "+f"(d[0]), "+f"(d[1]), "+f"(d[2]), "+f"(d[3])
        : "r"(a[0]), "r"(a[1]), "r"(a[2]), "r"(a[3]), "r"(b[0]), "r"(b[1]));
}
__device__ __forceinline__ void ldsm4(uint32_t* r, uint32_t a) {
    asm volatile("ldmatrix.sync.aligned.m8n8.x4.shared.b16 {%0,%1,%2,%3}, [%4];"
        : "=r"(r[0]), "=r"(r[1]), "=r"(r[2]), "=r"(r[3]) : "r"(a));
}

__device__ __forceinline__ void bsplit2(float a, float b, uint32_t& hi, uint32_t& lo) {
    __nv_bfloat162 h = __floats2bfloat162_rn(a, b);
    hi = *reinterpret_cast<uint32_t*>(&h);
    float ra = a - __bfloat162float(h.x);
    float rb = b - __bfloat162float(h.y);
    __nv_bfloat162 l = __floats2bfloat162_rn(ra, rb);
    lo = *reinterpret_cast<uint32_t*>(&l);
}

// ---- gemm1 smem map (64-row tiles, ROWB=304, K=144) ----
#define ROWB 304
#define OFF_BH 512
#define OFF_BL (OFF_BH + 38912)
#define OFF_A  (OFF_BL + 38912)        // 78336; 2 bufs x 38912 (hi 19456 + lo 19456)
#define OFF_EPI (OFF_A + 77824)        // 156160
#define SMEM_G1 (OFF_EPI + 33792)      // 189952 B

// ---- gemm2 smem map (32-row tiles, 256 thr, 2 blocks/SM, B in registers) ----
// B staged once at 512 (hi 34816 + lo 34816 = 69632), region then reused:
//   A bufs: 2 x 17408 (hi 8704 + lo 8704) at 512
//   epi: 32 x 132 floats at 512 + 34816
#define ROWB2 272
#define O2_A   512
#define O2_EPI (512 + 34816)           // 35328 (+16896 = 52224)
#define SMEM_G2 (512 + 69632)          // 70144 B per block

// ---------------- K0: segment bounds (batch sorted) ----------------
__global__ void k_bounds(const int* __restrict__ batch, int N) {
    int g = blockIdx.x * blockDim.x + threadIdx.x;
    if (g > NG) return;
    int lo = 0, hi = N;
    while (lo < hi) {
        int mid = (lo + hi) >> 1;
        if (batch[mid] < g) lo = mid + 1; else hi = mid;
    }
    g_seg[g] = lo;
}

// ---------------- K1: per-graph col means of x0 + lam1 = xm @ l1w^T ----------------
__global__ void k_lam1(const float* __restrict__ x, const float* __restrict__ pers0,
                       const float* __restrict__ l1w, int N) {
    __shared__ float s_sum[2][144];
    __shared__ float s_xm[144];
    int g  = blockIdx.x;
    int lo = g_seg[g], hi = g_seg[g + 1];
    int t  = threadIdx.x;
    int phase = t / 144, col = t - phase * 144;

    float acc = 0.f;
    if (col < 128) {
        const float* p = x + col;
        for (int r = lo + phase; r < hi; r += 2) acc += p[(size_t)r * 128];
    } else {
        int j = col - 128;
        int pp = j >> 1, c = j & 1;
        const float* p = pers0 + (size_t)pp * 2 * N + c;
        for (int r = lo + phase; r < hi; r += 2) acc += p[2 * (size_t)r];
    }
    s_sum[phase][col] = acc;
    __syncthreads();
    if (t < 144) {
        float cnt = (float)max(hi - lo, 1);
        s_xm[t] = (s_sum[0][t] + s_sum[1][t]) / cnt;
    }
    __syncthreads();
    if (t < 128) {
        const float* w = l1w + t * 144;
        float a = 0.f;
#pragma unroll 8
        for (int k = 0; k < 144; ++k) a += s_xm[k] * w[k];
        g_lam1[g * 128 + t] = a;
    }
}

// =============== K2: mma.sync GEMM1 (512 thr): h = relu(x0 @ g1w^T + g1b - lam1[g]) ===============
// 64-row tiles, 16 warps as 2M x 8N (warp: 32 rows x 16 cols). K=144 = 9 k16 steps.
__global__ __launch_bounds__(512, 1) void k_gemm1(
    const float* __restrict__ x, const float* __restrict__ pers0,
    const float* __restrict__ g1w, const float* __restrict__ g1b,
    const float* __restrict__ l2w, int N) {
    extern __shared__ char sm[];
    uint32_t su = smaddr(sm);
    float* sbias = (float*)sm;
    int g  = blockIdx.x;
    int lo = g_seg[g], hi = g_seg[g + 1];
    int tid = threadIdx.x;
    int wid = tid >> 5, l = tid & 31;
    int wm = wid & 1, wn = wid >> 1;           // 2M x 8N
    int seg = l >> 3, l7 = l & 7, gg = l >> 2, tg = l & 3;

    // stage B = g1w as bf16 hi/lo, row stride 304B
    for (int it = 0; it < 9; ++it) {
        int idx = tid + it * 512;            // [0, 128*36)
        int jr = idx / 36, k4 = idx - jr * 36;
        float4 v = ((const float4*)g1w)[idx];
        uint32_t h01, l01, h23, l23;
        bsplit2(v.x, v.y, h01, l01);
        bsplit2(v.z, v.w, h23, l23);
        int off = jr * ROWB + k4 * 8;
        *(uint2*)(sm + OFF_BH + off) = make_uint2(h01, h23);
        *(uint2*)(sm + OFF_BL + off) = make_uint2(l01, l23);
    }
    if (tid < 128) sbias[tid] = g1b[tid] - g_lam1[g * 128 + tid];

    // register prefetch of one 64-row x0 tile (row = tid>>3, k-eighth = tid&7)
    float4 xv[4]; float2 pv;
    int prow = tid >> 3, pk8 = tid & 7;
    auto loadRegs = [&](int r0i, int rem) {
        int rg = r0i + min(prow, rem - 1);
        const float4* xs = (const float4*)(x + (size_t)rg * 128) + pk8 * 4;
#pragma unroll
        for (int i = 0; i < 4; ++i) xv[i] = xs[i];
        pv = ((const float2*)pers0)[(size_t)pk8 * N + rg];
    };
    auto stsRegs = [&](int buf) {
        char* bh = sm + OFF_A + buf * 38912 + prow * ROWB;
        char* bl = bh + 19456;
#pragma unroll
        for (int i = 0; i < 4; ++i) {
            uint32_t h01, l01, h23, l23;
            bsplit2(xv[i].x, xv[i].y, h01, l01);
            bsplit2(xv[i].z, xv[i].w, h23, l23);
            *(uint2*)(bh + pk8 * 32 + i * 8) = make_uint2(h01, h23);
            *(uint2*)(bl + pk8 * 32 + i * 8) = make_uint2(l01, l23);
        }
        uint32_t h, lw;
        bsplit2(pv.x, pv.y, h, lw);
        *(uint32_t*)(bh + 256 + 4 * pk8) = h;
        *(uint32_t*)(bl + 256 + 4 * pk8) = lw;
    };

    float hs[16];
#pragma unroll
    for (int i = 0; i < 16; ++i) hs[i] = 0.f;

    uint32_t a_off = su + OFF_A  + (uint32_t)((wm * 32 + (seg & 1) * 8 + l7) * ROWB + (seg >> 1) * 16);
    uint32_t b_off = su + OFF_BH + (uint32_t)((wn * 16 + (seg >> 1) * 8 + l7) * ROWB + (seg & 1) * 16);

    if (lo < hi) { loadRegs(lo, min(64, hi - lo)); stsRegs(0); }
    __syncthreads();

    int t = 0;
    for (int r0 = lo; r0 < hi; r0 += 64, ++t) {
        int buf = t & 1;
        int nr0 = r0 + 64;
        bool havnext = nr0 < hi;
        if (havnext) loadRegs(nr0, min(64, hi - nr0));

        float D[4][4];
#pragma unroll
        for (int i = 0; i < 4; ++i)
#pragma unroll
            for (int q = 0; q < 4; ++q) D[i][q] = 0.f;

        uint32_t abase = a_off + buf * 38912;
#pragma unroll
        for (int ks = 0; ks < 9; ++ks) {
            uint32_t ah[2][4], al[2][4], bh4[4], bl4[4];
            ldsm4(ah[0], abase + ks * 32);
            ldsm4(al[0], abase + 19456 + ks * 32);
            ldsm4(ah[1], abase + 16 * ROWB + ks * 32);
            ldsm4(al[1], abase + 16 * ROWB + 19456 + ks * 32);
            ldsm4(bh4, b_off + ks * 32);
            ldsm4(bl4, b_off + 38912 + ks * 32);
#pragma unroll
            for (int m = 0; m < 2; ++m) {
                float* d0 = D[m * 2];
                float* d1 = D[m * 2 + 1];
                mma_bf16(d0, ah[m], bh4);
                mma_bf16(d1, ah[m], bh4 + 2);
                mma_bf16(d0, ah[m], bl4);
                mma_bf16(d1, ah[m], bl4 + 2);
                mma_bf16(d0, al[m], bh4);
                mma_bf16(d1, al[m], bh4 + 2);
            }
        }
        if (havnext) stsRegs(buf ^ 1);

        // single-phase epilogue: all 64 rows
        float* epi = (float*)(sm + OFF_EPI);
#pragma unroll
        for (int m = 0; m < 2; ++m)
#pragma unroll
        for (int h = 0; h < 2; ++h) {
            int d = m * 2 + h;
            int er = wm * 32 + m * 16 + gg;
            int c = wn * 16 + h * 8 + 2 * tg;
            *(float2*)(epi + er * 132 + c)       = make_float2(D[d][0], D[d][1]);
            *(float2*)(epi + (er + 8) * 132 + c) = make_float2(D[d][2], D[d][3]);
        }
        __syncthreads();
        {
            int r = tid >> 3, c0 = (tid & 7) * 16;
            int grow = r0 + r;
            if (grow < hi) {
                float v[16];
#pragma unroll
                for (int q = 0; q < 4; ++q)
                    *(float4*)(v + 4 * q) = *(const float4*)(epi + r * 132 + c0 + 4 * q);
                uint32_t hh[8], ll[8];
#pragma unroll
                for (int i = 0; i < 16; i += 2) {
                    float va = fmaxf(v[i]     + sbias[c0 + i],     0.f);
                    float vb = fmaxf(v[i + 1] + sbias[c0 + i + 1], 0.f);
                    hs[i] += va; hs[i + 1] += vb;
                    bsplit2(va, vb, hh[i >> 1], ll[i >> 1]);
                }
                size_t off = (size_t)grow * 128 + c0;
                *(uint4*)(g_hhi + off)     = make_uint4(hh[0], hh[1], hh[2], hh[3]);
                *(uint4*)(g_hhi + off + 8) = make_uint4(hh[4], hh[5], hh[6], hh[7]);
                *(uint4*)(g_hlo + off)     = make_uint4(ll[0], ll[1], ll[2], ll[3]);
                *(uint4*)(g_hlo + off + 8) = make_uint4(ll[4], ll[5], ll[6], ll[7]);
            }
        }
        __syncthreads();
    }

    // deterministic col-sum reduce -> hm -> lam2 = hm @ l2w^T
    float* red = (float*)(sm + OFF_EPI);
    __syncthreads();
#pragma unroll
    for (int i = 0; i < 16; ++i) red[tid * 16 + i] = hs[i];
    __syncthreads();
    if (tid < 128) {
        int o = tid >> 4, i = tid & 15;
        float s = 0.f;
        for (int ss = 0; ss < 64; ++ss) s += red[(ss * 8 + o) * 16 + i];
        float cnt = (float)max(hi - lo, 1);
        red[8192 + o * 16 + i] = s / cnt;
    }
    __syncthreads();
    if (tid < 128) {
        const float* w = l2w + tid * 128;
        const float* hm = red + 8192;
        float a = 0.f;
#pragma unroll 8
        for (int k = 0; k < 128; ++k) a += hm[k] * w[k];
        g_lam2[g * 128 + tid] = a;
    }
}

// =============== K4: mma.sync GEMM2 (256 thr, 2 blocks/SM): y0 = h @ g2w^T + g2b - lam2[g] ===============
// 32-row tiles, 8 warps as 1M x 8N (warp: 32 rows x 16 cols). K=128 = 8 k16 steps.
// B fragments resident in registers; BN sums decomposed (raw D/D^2 + analytic bias fixup).
__global__ __launch_bounds__(256, 2) void k_gemm2(
    const float* __restrict__ g2w, const float* __restrict__ g2b, int N) {
    extern __shared__ char sm[];
    uint32_t su = smaddr(sm);
    float* sbias = (float*)sm;
    int g  = blockIdx.x;
    int lo = g_seg[g], hi = g_seg[g + 1];
    int tid = threadIdx.x;
    int wid = tid >> 5, l = tid & 31;
    int wn = wid;                              // 1M x 8N
    int seg = l >> 3, l7 = l & 7, gg = l >> 2, tg = l & 3;

    // stage B = g2w bf16 hi/lo into smem once (hi at 512, lo at 512+34816)
    for (int it = 0; it < 16; ++it) {
        int idx = tid + it * 256;            // [0, 128*32)
        int jr = idx >> 5, k4 = idx & 31;
        float4 v = ((const float4*)g2w)[idx];
        uint32_t h01, l01, h23, l23;
        bsplit2(v.x, v.y, h01, l01);
        bsplit2(v.z, v.w, h23, l23);
        int off = jr * ROWB2 + k4 * 8;
        *(uint2*)(sm + 512 + off)         = make_uint2(h01, h23);
        *(uint2*)(sm + 512 + 34816 + off) = make_uint2(l01, l23);
    }
    if (tid < 128) sbias[tid] = g2b[tid] - g_lam2[g * 128 + tid];
    __syncthreads();

    // load B fragments to registers: per warp 16 cols x K=128, hi+lo = 64 regs
    uint32_t bh[8][4], bl[8][4];
    {
        uint32_t b_off = su + 512 + (uint32_t)((wn * 16 + (seg >> 1) * 8 + l7) * ROWB2 + (seg & 1) * 16);
#pragma unroll
        for (int ks = 0; ks < 8; ++ks) {
            ldsm4(bh[ks], b_off + ks * 32);
            ldsm4(bl[ks], b_off + 34816 + ks * 32);
        }
    }
    __syncthreads();   // B smem dead; region now reused for A buffers

    // A staging via cp.async from pre-split h arrays (32 rows per tile)
    auto stageA = [&](int r0i, int rem, int buf) {
#pragma unroll
        for (int hl = 0; hl < 2; ++hl) {
            const __nv_bfloat16* src = hl ? g_hlo : g_hhi;
            uint32_t base = su + O2_A + buf * 17408 + hl * 8704;
#pragma unroll
            for (int it = 0; it < 2; ++it) {
                int idx = tid + it * 256;        // [0, 32*16)
                int r = idx >> 4, u = idx & 15;
                int rc = (r < rem) ? r : 0;
                cp16(base + r * ROWB2 + u * 16,
                     src + (size_t)(r0i + rc) * 128 + u * 8, (r < rem) ? 16 : 0);
            }
        }
    };

    float sD[4] = {0.f, 0.f, 0.f, 0.f}, sQ[4] = {0.f, 0.f, 0.f, 0.f};

    uint32_t a_off = su + O2_A + (uint32_t)(((seg & 1) * 8 + l7) * ROWB2 + (seg >> 1) * 16);

    if (lo < hi) { stageA(lo, min(32, hi - lo), 0); CP_COMMIT(); CP_WAIT0(); }
    __syncthreads();

    int t = 0;
    for (int r0 = lo; r0 < hi; r0 += 32, ++t) {
        int buf = t & 1;
        int nr0 = r0 + 32;
        bool havnext = nr0 < hi;
        if (havnext) { stageA(nr0, min(32, hi - nr0), buf ^ 1); CP_COMMIT(); }

        float D[4][4];
#pragma unroll
        for (int i = 0; i < 4; ++i)
#pragma unroll
            for (int q = 0; q < 4; ++q) D[i][q] = 0.f;

        uint32_t abase = a_off + buf * 17408;
#pragma unroll
        for (int ks = 0; ks < 8; ++ks) {
            uint32_t ah0[4], al0[4], ah1[4], al1[4];
            ldsm4(ah0, abase + ks * 32);
            ldsm4(al0, abase + 8704 + ks * 32);
            ldsm4(ah1, abase + 16 * ROWB2 + ks * 32);
            ldsm4(al1, abase + 16 * ROWB2 + 8704 + ks * 32);
            mma_bf16(D[0], ah0, bh[ks]);     mma_bf16(D[1], ah0, bh[ks] + 2);
            mma_bf16(D[0], ah0, bl[ks]);     mma_bf16(D[1], ah0, bl[ks] + 2);
            mma_bf16(D[0], al0, bh[ks]);     mma_bf16(D[1], al0, bh[ks] + 2);
            mma_bf16(D[2], ah1, bh[ks]);     mma_bf16(D[3], ah1, bh[ks] + 2);
            mma_bf16(D[2], ah1, bl[ks]);     mma_bf16(D[3], ah1, bl[ks] + 2);
            mma_bf16(D[2], al1, bh[ks]);     mma_bf16(D[3], al1, bh[ks] + 2);
        }

        // accumulate raw sums (pre-bias) with row-validity masks
#pragma unroll
        for (int m = 0; m < 2; ++m) {
            int rA = r0 + m * 16 + gg;
            bool v0 = rA < hi, v1 = (rA + 8) < hi;
#pragma unroll
            for (int h = 0; h < 2; ++h) {
                float* d = D[m * 2 + h];
                if (v0) {
                    sD[h * 2 + 0] += d[0]; sQ[h * 2 + 0] += d[0] * d[0];
                    sD[h * 2 + 1] += d[1]; sQ[h * 2 + 1] += d[1] * d[1];
                }
                if (v1) {
                    sD[h * 2 + 0] += d[2]; sQ[h * 2 + 0] += d[2] * d[2];
                    sD[h * 2 + 1] += d[3]; sQ[h * 2 + 1] += d[3] * d[3];
                }
            }
        }

        // epilogue: store y via smem roundtrip (bias applied by reading thread)
        float* epi = (float*)(sm + O2_EPI);
#pragma unroll
        for (int m = 0; m < 2; ++m)
#pragma unroll
        for (int h = 0; h < 2; ++h) {
            float* d = D[m * 2 + h];
            int er = m * 16 + gg;
            int c = wn * 16 + h * 8 + 2 * tg;
            *(float2*)(epi + er * 132 + c)       = make_float2(d[0], d[1]);
            *(float2*)(epi + (er + 8) * 132 + c) = make_float2(d[2], d[3]);
        }
        __syncthreads();
        {
            int r = tid >> 3, c0 = (tid & 7) * 16;
            int grow = r0 + r;
            if (grow < hi) {
                float v[16];
#pragma unroll
                for (int q = 0; q < 4; ++q)
                    *(float4*)(v + 4 * q) = *(const float4*)(epi + r * 132 + c0 + 4 * q);
#pragma unroll
                for (int i = 0; i < 16; ++i) v[i] += sbias[c0 + i];
                float* dst = g_y + (size_t)grow * 128 + c0;
#pragma unroll
                for (int q = 0; q < 4; ++q) *(float4*)(dst + 4 * q) = *(float4*)(v + 4 * q);
            }
        }
        if (havnext) CP_WAIT0();
        __syncthreads();
    }

    // deterministic BN partials: fixed-order reduce of raw sums + analytic bias fixup
    float* red = (float*)(sm + O2_EPI);
    __syncthreads();
#pragma unroll
    for (int i = 0; i < 4; ++i) { red[tid * 8 + i] = sD[i]; red[tid * 8 + 4 + i] = sQ[i]; }
    __syncthreads();
    if (tid < 128) {
        int c = tid;
        int wn_ = c >> 4, cc = c & 15;
        int tg_ = (cc & 7) >> 1, s = ((cc >> 3) << 1) + (cc & 1);
        float sum = 0.f, sq = 0.f;
#pragma unroll
        for (int gg_ = 0; gg_ < 8; ++gg_) {
            int tt = wn_ * 32 + gg_ * 4 + tg_;
            sum += red[tt * 8 + s];
            sq  += red[tt * 8 + 4 + s];
        }
        float b = sbias[c];
        float cnt = (float)(hi - lo);
        g_psum[g * 128 + c] = sum + cnt * b;
        g_psq[g * 128 + c]  = sq + 2.f * b * sum + cnt * b * b;
    }
}

// ---------------- K5: BN stats -> scale/shift ----------------
__global__ void k_stats(const float* __restrict__ bn_g, const float* __restrict__ bn_b, int N) {
    int t = threadIdx.x;  // 128
    float s = 0.f, q = 0.f;
    for (int g = 0; g < NG; ++g) {
        s += g_psum[g * 128 + t];
        q += g_psq[g * 128 + t];
    }
    float invN = 1.f / (float)N;
    float mu  = s * invN;
    float var = fmaxf(q * invN - mu * mu, 0.f);
    float sc  = rsqrtf(var + BN_EPS) * bn_g[t];
    g_scale[t] = sc;
    g_shift[t] = bn_b[t] - mu * sc;
}

// ---------------- K6: out = x + y0*scale + shift ----------------
__global__ void k_out(const float* __restrict__ x, float* __restrict__ out, int total4) {
    int i = blockIdx.x * blockDim.x + threadIdx.x;
    if (i >= total4) return;
    int j4 = i & 31;
    float4 sc = ((const float4*)g_scale)[j4];
    float4 sh = ((const float4*)g_shift)[j4];
    float4 xv = ((const float4*)x)[i];
    float4 yv = ((const float4*)g_y)[i];
    float4 o;
    o.x = xv.x + yv.x * sc.x + sh.x;
    o.y = xv.y + yv.y * sc.y + sh.y;
    o.z = xv.z + yv.z * sc.z + sh.z;
    o.w = xv.w + yv.w * sc.w + sh.w;
    ((float4*)out)[i] = o;
}

// ---------------- launch ----------------
extern "C" void kernel_launch(void* const* d_in, const int* in_sizes, int n_in,
                              void* d_out, int out_size) {
    const float* x     = (const float*)d_in[0];
    const int*   batch = (const int*)d_in[1];
    const float* pers0 = (const float*)d_in[2];
    const float* g1w   = (const float*)d_in[3];
    const float* g1b   = (const float*)d_in[4];
    const float* l1w   = (const float*)d_in[5];
    const float* g2w   = (const float*)d_in[6];
    const float* g2b   = (const float*)d_in[7];
    const float* l2w   = (const float*)d_in[8];
    const float* bng   = (const float*)d_in[9];
    const float* bnb   = (const float*)d_in[10];
    float* out = (float*)d_out;
    int N = in_sizes[0] / 128;

    cudaFuncSetAttribute(k_gemm1, cudaFuncAttributeMaxDynamicSharedMemorySize, SMEM_G1);
    cudaFuncSetAttribute(k_gemm2, cudaFuncAttributeMaxDynamicSharedMemorySize, SMEM_G2);

    k_bounds<<<(NG + 256) / 256, 256>>>(batch, N);
    k_lam1<<<NG, 288>>>(x, pers0, l1w, N);
    k_gemm1<<<NG, 512, SMEM_G1>>>(x, pers0, g1w, g1b, l2w, N);
    k_gemm2<<<NG, 256, SMEM_G2>>>(g2w, g2b, N);
    k_stats<<<1, 128>>>(bng, bnb, N);
    int total4 = N * 32;
    k_out<<<(total4 + 255) / 256, 256>>>(x, out, total4);
}

// round 15
// speedup vs baseline: 1.1354x; 1.0583x over previous
#include <cuda_runtime.h>
#include <cuda_bf16.h>
#include <cstdint>

#define NG   2048
#define MAXN 500000
#define BN_EPS 1e-5f

typedef unsigned long long ull;

// ---------------- scratch (device globals; no allocation allowed) ----------------
__device__ __align__(16) __nv_bfloat16 g_hhi[(size_t)MAXN * 128];
__device__ __align__(16) __nv_bfloat16 g_hlo[(size_t)MAXN * 128];
__device__ __align__(16) float g_y[(size_t)MAXN * 128];
__device__ __align__(16) float g_lam1[NG * 128];
__device__ __align__(16) float g_lam2[NG * 128];
__device__ __align__(16) float g_psum[NG * 128];
__device__ __align__(16) float g_psq[NG * 128];
__device__ __align__(16) float g_scale[128];
__device__ __align__(16) float g_shift[128];
__device__ int g_seg[NG + 1];

// ---------------- helpers ----------------
__device__ __forceinline__ uint32_t smaddr(const void* p) {
    return (uint32_t)__cvta_generic_to_shared(p);
}
__device__ __forceinline__ void cp16(uint32_t d, const void* s, int n) {
    asm volatile("cp.async.ca.shared.global [%0], [%1], 16, %2;\n" :: "r"(d), "l"(s), "r"(n));
}
#define CP_COMMIT() asm volatile("cp.async.commit_group;\n" ::: "memory")
#define CP_WAIT0()  asm volatile("cp.async.wait_group 0;\n" ::: "memory")

__device__ __forceinline__ void mma_bf16(float* d, const uint32_t* a, const uint32_t* b) {
    asm volatile(
        "mma.sync.aligned.m16n8k16.row.col.f32.bf16.bf16.f32 "
        "{%0,%1,%2,%3}, {%4,%5,%6,%7}, {%8,%9}, {%0,%1,%2,%3};"
        : "+f"(d[0]), "+f"(d[1]), "+f"(d[2]), "+f"(d[3])
        : "r"(a[0]), "r"(a[1]), "r"(a[2]), "r"(a[3]), "r"(b[0]), "r"(b[1]));
}
__device__ __forceinline__ void ldsm4(uint32_t* r, uint32_t a) {
    asm volatile("ldmatrix.sync.aligned.m8n8.x4.shared.b16 {%0,%1,%2,%3}, [%4];"
        : "=r"(r[0]), "=r"(r[1]), "=r"(r[2]), "=r"(r[3]) : "r"(a));
}

__device__ __forceinline__ void bsplit2(float a, float b, uint32_t& hi, uint32_t& lo) {
    __nv_bfloat162 h = __floats2bfloat162_rn(a, b);
    hi = *reinterpret_cast<uint32_t*>(&h);
    float ra = a - __bfloat162float(h.x);
    float rb = b - __bfloat162float(h.y);
    __nv_bfloat162 l = __floats2bfloat162_rn(ra, rb);
    lo = *reinterpret_cast<uint32_t*>(&l);
}

// ---- gemm1 smem map (32-row tiles, 256 thr, 2 blocks/SM, Bhi in regs, Blo in smem) ----
// region R1 at 512 (38912 B): staged with BH first, then reused as A bufs
//   A bufs: 2 x 19456 (hi 9728 + lo 9728)
// BL resident at 512+38912 = 39424 (38912 B)
// epi at 39424+38912 = 78336 (16896 B)
#define ROWB 304
#define O1_R1  512
#define O1_BL  (512 + 38912)            // 39424
#define O1_EPI (O1_BL + 38912)          // 78336
#define SMEM_G1 (O1_EPI + 16896)        // 95232 B per block

// ---- gemm2 smem map (32-row tiles, 256 thr, 2 blocks/SM, B in registers) ----
#define ROWB2 272
#define O2_A   512
#define O2_EPI (512 + 34816)            // 35328
#define SMEM_G2 (512 + 69632)           // 70144 B per block

// ---------------- K0: segment bounds (batch sorted) ----------------
__global__ void k_bounds(const int* __restrict__ batch, int N) {
    int g = blockIdx.x * blockDim.x + threadIdx.x;
    if (g > NG) return;
    int lo = 0, hi = N;
    while (lo < hi) {
        int mid = (lo + hi) >> 1;
        if (batch[mid] < g) lo = mid + 1; else hi = mid;
    }
    g_seg[g] = lo;
}

// ---------------- K1: per-graph col means of x0 + lam1 = xm @ l1w^T ----------------
__global__ void k_lam1(const float* __restrict__ x, const float* __restrict__ pers0,
                       const float* __restrict__ l1w, int N) {
    __shared__ float s_sum[2][144];
    __shared__ float s_xm[144];
    int g  = blockIdx.x;
    int lo = g_seg[g], hi = g_seg[g + 1];
    int t  = threadIdx.x;
    int phase = t / 144, col = t - phase * 144;

    float acc = 0.f;
    if (col < 128) {
        const float* p = x + col;
        for (int r = lo + phase; r < hi; r += 2) acc += p[(size_t)r * 128];
    } else {
        int j = col - 128;
        int pp = j >> 1, c = j & 1;
        const float* p = pers0 + (size_t)pp * 2 * N + c;
        for (int r = lo + phase; r < hi; r += 2) acc += p[2 * (size_t)r];
    }
    s_sum[phase][col] = acc;
    __syncthreads();
    if (t < 144) {
        float cnt = (float)max(hi - lo, 1);
        s_xm[t] = (s_sum[0][t] + s_sum[1][t]) / cnt;
    }
    __syncthreads();
    if (t < 128) {
        const float* w = l1w + t * 144;
        float a = 0.f;
#pragma unroll 8
        for (int k = 0; k < 144; ++k) a += s_xm[k] * w[k];
        g_lam1[g * 128 + t] = a;
    }
}

// =============== K2: mma.sync GEMM1 (256 thr, 2 blocks/SM): h = relu(x0 @ g1w^T + g1b - lam1[g]) ===============
// 32-row tiles, 8 warps as 1M x 8N (warp: 32 rows x 16 cols). K=144 = 9 k16 steps.
// Bhi fragments in REGISTERS (loaded once); Blo read from resident smem (1 ldsm/ks).
__global__ __launch_bounds__(256, 2) void k_gemm1(
    const float* __restrict__ x, const float* __restrict__ pers0,
    const float* __restrict__ g1w, const float* __restrict__ g1b,
    const float* __restrict__ l2w, int N) {
    extern __shared__ char sm[];
    uint32_t su = smaddr(sm);
    float* sbias = (float*)sm;
    int g  = blockIdx.x;
    int lo = g_seg[g], hi = g_seg[g + 1];
    int tid = threadIdx.x;
    int wid = tid >> 5, l = tid & 31;
    int wn = wid;                              // 1M x 8N
    int seg = l >> 3, l7 = l & 7, gg = l >> 2, tg = l & 3;

    // stage B = g1w as bf16: BH into R1 (temp), BL into resident region
    for (int it = 0; it < 18; ++it) {
        int idx = tid + it * 256;            // [0, 128*36)
        int jr = idx / 36, k4 = idx - jr * 36;
        float4 v = ((const float4*)g1w)[idx];
        uint32_t h01, l01, h23, l23;
        bsplit2(v.x, v.y, h01, l01);
        bsplit2(v.z, v.w, h23, l23);
        int off = jr * ROWB + k4 * 8;
        *(uint2*)(sm + O1_R1 + off) = make_uint2(h01, h23);
        *(uint2*)(sm + O1_BL + off) = make_uint2(l01, l23);
    }
    if (tid < 128) sbias[tid] = g1b[tid] - g_lam1[g * 128 + tid];
    __syncthreads();

    // load Bhi fragments to registers: per warp 16 cols x K=144 = 36 regs
    uint32_t bh[9][4];
    uint32_t blo_off;
    {
        uint32_t bidx = (uint32_t)((wn * 16 + (seg >> 1) * 8 + l7) * ROWB + (seg & 1) * 16);
        uint32_t b_off = su + O1_R1 + bidx;
        blo_off = su + O1_BL + bidx;
#pragma unroll
        for (int ks = 0; ks < 9; ++ks) ldsm4(bh[ks], b_off + ks * 32);
    }
    __syncthreads();   // BH smem dead; R1 now reused for A buffers

    // register prefetch of one 32-row x0 tile (row = tid>>3, k-eighth = tid&7)
    float4 xv[4]; float2 pv;
    int prow = tid >> 3, pk8 = tid & 7;
    auto loadRegs = [&](int r0i, int rem) {
        int rg = r0i + min(prow, rem - 1);
        const float4* xs = (const float4*)(x + (size_t)rg * 128) + pk8 * 4;
#pragma unroll
        for (int i = 0; i < 4; ++i) xv[i] = xs[i];
        pv = ((const float2*)pers0)[(size_t)pk8 * N + rg];
    };
    auto stsRegs = [&](int buf) {
        char* bhd = sm + O1_R1 + buf * 19456 + prow * ROWB;
        char* bld = bhd + 9728;
#pragma unroll
        for (int i = 0; i < 4; ++i) {
            uint32_t h01, l01, h23, l23;
            bsplit2(xv[i].x, xv[i].y, h01, l01);
            bsplit2(xv[i].z, xv[i].w, h23, l23);
            *(uint2*)(bhd + pk8 * 32 + i * 8) = make_uint2(h01, h23);
            *(uint2*)(bld + pk8 * 32 + i * 8) = make_uint2(l01, l23);
        }
        uint32_t h, lw;
        bsplit2(pv.x, pv.y, h, lw);
        *(uint32_t*)(bhd + 256 + 4 * pk8) = h;
        *(uint32_t*)(bld + 256 + 4 * pk8) = lw;
    };

    float hs[16];
#pragma unroll
    for (int i = 0; i < 16; ++i) hs[i] = 0.f;

    uint32_t a_off = su + O1_R1 + (uint32_t)(((seg & 1) * 8 + l7) * ROWB + (seg >> 1) * 16);

    if (lo < hi) { loadRegs(lo, min(32, hi - lo)); stsRegs(0); }
    __syncthreads();

    int t = 0;
    for (int r0 = lo; r0 < hi; r0 += 32, ++t) {
        int buf = t & 1;
        int nr0 = r0 + 32;
        bool havnext = nr0 < hi;
        if (havnext) loadRegs(nr0, min(32, hi - nr0));

        float D[4][4];
#pragma unroll
        for (int i = 0; i < 4; ++i)
#pragma unroll
            for (int q = 0; q < 4; ++q) D[i][q] = 0.f;

        uint32_t abase = a_off + buf * 19456;
#pragma unroll
        for (int ks = 0; ks < 9; ++ks) {
            uint32_t ah0[4], al0[4], ah1[4], al1[4], blo[4];
            ldsm4(ah0, abase + ks * 32);
            ldsm4(al0, abase + 9728 + ks * 32);
            ldsm4(ah1, abase + 16 * ROWB + ks * 32);
            ldsm4(al1, abase + 16 * ROWB + 9728 + ks * 32);
            ldsm4(blo, blo_off + ks * 32);
            mma_bf16(D[0], ah0, bh[ks]);   mma_bf16(D[1], ah0, bh[ks] + 2);
            mma_bf16(D[0], ah0, blo);      mma_bf16(D[1], ah0, blo + 2);
            mma_bf16(D[0], al0, bh[ks]);   mma_bf16(D[1], al0, bh[ks] + 2);
            mma_bf16(D[2], ah1, bh[ks]);   mma_bf16(D[3], ah1, bh[ks] + 2);
            mma_bf16(D[2], ah1, blo);      mma_bf16(D[3], ah1, blo + 2);
            mma_bf16(D[2], al1, bh[ks]);   mma_bf16(D[3], al1, bh[ks] + 2);
        }
        if (havnext) stsRegs(buf ^ 1);

        // epilogue: 32 rows through smem; relu + h hi/lo store + col sums
        float* epi = (float*)(sm + O1_EPI);
#pragma unroll
        for (int m = 0; m < 2; ++m)
#pragma unroll
        for (int h = 0; h < 2; ++h) {
            float* d = D[m * 2 + h];
            int er = m * 16 + gg;
            int c = wn * 16 + h * 8 + 2 * tg;
            *(float2*)(epi + er * 132 + c)       = make_float2(d[0], d[1]);
            *(float2*)(epi + (er + 8) * 132 + c) = make_float2(d[2], d[3]);
        }
        __syncthreads();
        {
            int r = tid >> 3, c0 = (tid & 7) * 16;
            int grow = r0 + r;
            if (grow < hi) {
                float v[16];
#pragma unroll
                for (int q = 0; q < 4; ++q)
                    *(float4*)(v + 4 * q) = *(const float4*)(epi + r * 132 + c0 + 4 * q);
                uint32_t hh[8], ll[8];
#pragma unroll
                for (int i = 0; i < 16; i += 2) {
                    float va = fmaxf(v[i]     + sbias[c0 + i],     0.f);
                    float vb = fmaxf(v[i + 1] + sbias[c0 + i + 1], 0.f);
                    hs[i] += va; hs[i + 1] += vb;
                    bsplit2(va, vb, hh[i >> 1], ll[i >> 1]);
                }
                size_t off = (size_t)grow * 128 + c0;
                *(uint4*)(g_hhi + off)     = make_uint4(hh[0], hh[1], hh[2], hh[3]);
                *(uint4*)(g_hhi + off + 8) = make_uint4(hh[4], hh[5], hh[6], hh[7]);
                *(uint4*)(g_hlo + off)     = make_uint4(ll[0], ll[1], ll[2], ll[3]);
                *(uint4*)(g_hlo + off + 8) = make_uint4(ll[4], ll[5], ll[6], ll[7]);
            }
        }
        __syncthreads();
    }

    // deterministic col-sum reduce -> hm -> lam2 = hm @ l2w^T
    float* red = (float*)(sm + O1_EPI);
    __syncthreads();
#pragma unroll
    for (int i = 0; i < 16; ++i) red[tid * 16 + i] = hs[i];
    __syncthreads();
    if (tid < 128) {
        int o = tid >> 4, i = tid & 15;
        float s = 0.f;
        for (int rr = 0; rr < 32; ++rr) s += red[(rr * 8 + o) * 16 + i];
        float cnt = (float)max(hi - lo, 1);
        red[4096 + o * 16 + i] = s / cnt;
    }
    __syncthreads();
    if (tid < 128) {
        const float* w = l2w + tid * 128;
        const float* hm = red + 4096;
        float a = 0.f;
#pragma unroll 8
        for (int k = 0; k < 128; ++k) a += hm[k] * w[k];
        g_lam2[g * 128 + tid] = a;
    }
}

// =============== K4: mma.sync GEMM2 (256 thr, 2 blocks/SM): y0 = h @ g2w^T + g2b - lam2[g] ===============
// 32-row tiles, 8 warps as 1M x 8N (warp: 32 rows x 16 cols). K=128 = 8 k16 steps.
// B fragments resident in registers; BN sums decomposed (raw D/D^2 + analytic bias fixup).
__global__ __launch_bounds__(256, 2) void k_gemm2(
    const float* __restrict__ g2w, const float* __restrict__ g2b, int N) {
    extern __shared__ char sm[];
    uint32_t su = smaddr(sm);
    float* sbias = (float*)sm;
    int g  = blockIdx.x;
    int lo = g_seg[g], hi = g_seg[g + 1];
    int tid = threadIdx.x;
    int wid = tid >> 5, l = tid & 31;
    int wn = wid;                              // 1M x 8N
    int seg = l >> 3, l7 = l & 7, gg = l >> 2, tg = l & 3;

    // stage B = g2w bf16 hi/lo into smem once (hi at 512, lo at 512+34816)
    for (int it = 0; it < 16; ++it) {
        int idx = tid + it * 256;            // [0, 128*32)
        int jr = idx >> 5, k4 = idx & 31;
        float4 v = ((const float4*)g2w)[idx];
        uint32_t h01, l01, h23, l23;
        bsplit2(v.x, v.y, h01, l01);
        bsplit2(v.z, v.w, h23, l23);
        int off = jr * ROWB2 + k4 * 8;
        *(uint2*)(sm + 512 + off)         = make_uint2(h01, h23);
        *(uint2*)(sm + 512 + 34816 + off) = make_uint2(l01, l23);
    }
    if (tid < 128) sbias[tid] = g2b[tid] - g_lam2[g * 128 + tid];
    __syncthreads();

    // load B fragments to registers: per warp 16 cols x K=128, hi+lo = 64 regs
    uint32_t bh[8][4], bl[8][4];
    {
        uint32_t b_off = su + 512 + (uint32_t)((wn * 16 + (seg >> 1) * 8 + l7) * ROWB2 + (seg & 1) * 16);
#pragma unroll
        for (int ks = 0; ks < 8; ++ks) {
            ldsm4(bh[ks], b_off + ks * 32);
            ldsm4(bl[ks], b_off + 34816 + ks * 32);
        }
    }
    __syncthreads();   // B smem dead; region now reused for A buffers

    // A staging via cp.async from pre-split h arrays (32 rows per tile)
    auto stageA = [&](int r0i, int rem, int buf) {
#pragma unroll
        for (int hl = 0; hl < 2; ++hl) {
            const __nv_bfloat16* src = hl ? g_hlo : g_hhi;
            uint32_t base = su + O2_A + buf * 17408 + hl * 8704;
#pragma unroll
            for (int it = 0; it < 2; ++it) {
                int idx = tid + it * 256;        // [0, 32*16)
                int r = idx >> 4, u = idx & 15;
                int rc = (r < rem) ? r : 0;
                cp16(base + r * ROWB2 + u * 16,
                     src + (size_t)(r0i + rc) * 128 + u * 8, (r < rem) ? 16 : 0);
            }
        }
    };

    float sD[4] = {0.f, 0.f, 0.f, 0.f}, sQ[4] = {0.f, 0.f, 0.f, 0.f};

    uint32_t a_off = su + O2_A + (uint32_t)(((seg & 1) * 8 + l7) * ROWB2 + (seg >> 1) * 16);

    if (lo < hi) { stageA(lo, min(32, hi - lo), 0); CP_COMMIT(); CP_WAIT0(); }
    __syncthreads();

    int t = 0;
    for (int r0 = lo; r0 < hi; r0 += 32, ++t) {
        int buf = t & 1;
        int nr0 = r0 + 32;
        bool havnext = nr0 < hi;
        if (havnext) { stageA(nr0, min(32, hi - nr0), buf ^ 1); CP_COMMIT(); }

        float D[4][4];
#pragma unroll
        for (int i = 0; i < 4; ++i)
#pragma unroll
            for (int q = 0; q < 4; ++q) D[i][q] = 0.f;

        uint32_t abase = a_off + buf * 17408;
#pragma unroll
        for (int ks = 0; ks < 8; ++ks) {
            uint32_t ah0[4], al0[4], ah1[4], al1[4];
            ldsm4(ah0, abase + ks * 32);
            ldsm4(al0, abase + 8704 + ks * 32);
            ldsm4(ah1, abase + 16 * ROWB2 + ks * 32);
            ldsm4(al1, abase + 16 * ROWB2 + 8704 + ks * 32);
            mma_bf16(D[0], ah0, bh[ks]);     mma_bf16(D[1], ah0, bh[ks] + 2);
            mma_bf16(D[0], ah0, bl[ks]);     mma_bf16(D[1], ah0, bl[ks] + 2);
            mma_bf16(D[0], al0, bh[ks]);     mma_bf16(D[1], al0, bh[ks] + 2);
            mma_bf16(D[2], ah1, bh[ks]);     mma_bf16(D[3], ah1, bh[ks] + 2);
            mma_bf16(D[2], ah1, bl[ks]);     mma_bf16(D[3], ah1, bl[ks] + 2);
            mma_bf16(D[2], al1, bh[ks]);     mma_bf16(D[3], al1, bh[ks] + 2);
        }

        // accumulate raw sums (pre-bias) with row-validity masks
#pragma unroll
        for (int m = 0; m < 2; ++m) {
            int rA = r0 + m * 16 + gg;
            bool v0 = rA < hi, v1 = (rA + 8) < hi;
#pragma unroll
            for (int h = 0; h < 2; ++h) {
                float* d = D[m * 2 + h];
                if (v0) {
                    sD[h * 2 + 0] += d[0]; sQ[h * 2 + 0] += d[0] * d[0];
                    sD[h * 2 + 1] += d[1]; sQ[h * 2 + 1] += d[1] * d[1];
                }
                if (v1) {
                    sD[h * 2 + 0] += d[2]; sQ[h * 2 + 0] += d[2] * d[2];
                    sD[h * 2 + 1] += d[3]; sQ[h * 2 + 1] += d[3] * d[3];
                }
            }
        }

        // epilogue: store y via smem roundtrip (bias applied by reading thread)
        float* epi = (float*)(sm + O2_EPI);
#pragma unroll
        for (int m = 0; m < 2; ++m)
#pragma unroll
        for (int h = 0; h < 2; ++h) {
            float* d = D[m * 2 + h];
            int er = m * 16 + gg;
            int c = wn * 16 + h * 8 + 2 * tg;
            *(float2*)(epi + er * 132 + c)       = make_float2(d[0], d[1]);
            *(float2*)(epi + (er + 8) * 132 + c) = make_float2(d[2], d[3]);
        }
        __syncthreads();
        {
            int r = tid >> 3, c0 = (tid & 7) * 16;
            int grow = r0 + r;
            if (grow < hi) {
                float v[16];
#pragma unroll
                for (int q = 0; q < 4; ++q)
                    *(float4*)(v + 4 * q) = *(const float4*)(epi + r * 132 + c0 + 4 * q);
#pragma unroll
                for (int i = 0; i < 16; ++i) v[i] += sbias[c0 + i];
                float* dst = g_y + (size_t)grow * 128 + c0;
#pragma unroll
                for (int q = 0; q < 4; ++q) *(float4*)(dst + 4 * q) = *(float4*)(v + 4 * q);
            }
        }
        if (havnext) CP_WAIT0();
        __syncthreads();
    }

    // deterministic BN partials: fixed-order reduce of raw sums + analytic bias fixup
    float* red = (float*)(sm + O2_EPI);
    __syncthreads();
#pragma unroll
    for (int i = 0; i < 4; ++i) { red[tid * 8 + i] = sD[i]; red[tid * 8 + 4 + i] = sQ[i]; }
    __syncthreads();
    if (tid < 128) {
        int c = tid;
        int wn_ = c >> 4, cc = c & 15;
        int tg_ = (cc & 7) >> 1, s = ((cc >> 3) << 1) + (cc & 1);
        float sum = 0.f, sq = 0.f;
#pragma unroll
        for (int gg_ = 0; gg_ < 8; ++gg_) {
            int tt = wn_ * 32 + gg_ * 4 + tg_;
            sum += red[tt * 8 + s];
            sq  += red[tt * 8 + 4 + s];
        }
        float b = sbias[c];
        float cnt = (float)(hi - lo);
        g_psum[g * 128 + c] = sum + cnt * b;
        g_psq[g * 128 + c]  = sq + 2.f * b * sum + cnt * b * b;
    }
}

// ---------------- K5: BN stats -> scale/shift ----------------
__global__ void k_stats(const float* __restrict__ bn_g, const float* __restrict__ bn_b, int N) {
    int t = threadIdx.x;  // 128
    float s = 0.f, q = 0.f;
    for (int g = 0; g < NG; ++g) {
        s += g_psum[g * 128 + t];
        q += g_psq[g * 128 + t];
    }
    float invN = 1.f / (float)N;
    float mu  = s * invN;
    float var = fmaxf(q * invN - mu * mu, 0.f);
    float sc  = rsqrtf(var + BN_EPS) * bn_g[t];
    g_scale[t] = sc;
    g_shift[t] = bn_b[t] - mu * sc;
}

// ---------------- K6: out = x + y0*scale + shift ----------------
__global__ void k_out(const float* __restrict__ x, float* __restrict__ out, int total4) {
    int i = blockIdx.x * blockDim.x + threadIdx.x;
    if (i >= total4) return;
    int j4 = i & 31;
    float4 sc = ((const float4*)g_scale)[j4];
    float4 sh = ((const float4*)g_shift)[j4];
    float4 xv = ((const float4*)x)[i];
    float4 yv = ((const float4*)g_y)[i];
    float4 o;
    o.x = xv.x + yv.x * sc.x + sh.x;
    o.y = xv.y + yv.y * sc.y + sh.y;
    o.z = xv.z + yv.z * sc.z + sh.z;
    o.w = xv.w + yv.w * sc.w + sh.w;
    ((float4*)out)[i] = o;
}

// ---------------- launch ----------------
extern "C" void kernel_launch(void* const* d_in, const int* in_sizes, int n_in,
                              void* d_out, int out_size) {
    const float* x     = (const float*)d_in[0];
    const int*   batch = (const int*)d_in[1];
    const float* pers0 = (const float*)d_in[2];
    const float* g1w   = (const float*)d_in[3];
    const float* g1b   = (const float*)d_in[4];
    const float* l1w   = (const float*)d_in[5];
    const float* g2w   = (const float*)d_in[6];
    const float* g2b   = (const float*)d_in[7];
    const float* l2w   = (const float*)d_in[8];
    const float* bng   = (const float*)d_in[9];
    const float* bnb   = (const float*)d_in[10];
    float* out = (float*)d_out;
    int N = in_sizes[0] / 128;

    cudaFuncSetAttribute(k_gemm1, cudaFuncAttributeMaxDynamicSharedMemorySize, SMEM_G1);
    cudaFuncSetAttribute(k_gemm2, cudaFuncAttributeMaxDynamicSharedMemorySize, SMEM_G2);

    k_bounds<<<(NG + 256) / 256, 256>>>(batch, N);
    k_lam1<<<NG, 288>>>(x, pers0, l1w, N);
    k_gemm1<<<NG, 256, SMEM_G1>>>(x, pers0, g1w, g1b, l2w, N);
    k_gemm2<<<NG, 256, SMEM_G2>>>(g2w, g2b, N);
    k_stats<<<1, 128>>>(bng, bnb, N);
    int total4 = N * 32;
    k_out<<<(total4 + 255) / 256, 256>>>(x, out, total4);
}

// round 16
// speedup vs baseline: 1.2720x; 1.1203x over previous
#include <cuda_runtime.h>
#include <cuda_bf16.h>
#include <cstdint>

#define NG   2048
#define MAXN 500000
#define BN_EPS 1e-5f

typedef unsigned long long ull;

// ---------------- scratch (device globals; no allocation allowed) ----------------
__device__ __align__(16) __nv_bfloat16 g_hhi[(size_t)MAXN * 128];
__device__ __align__(16) __nv_bfloat16 g_hlo[(size_t)MAXN * 128];
__device__ __align__(16) float g_y[(size_t)MAXN * 128];
__device__ __align__(16) float g_lam1[NG * 128];
__device__ __align__(16) float g_lam2[NG * 128];
__device__ __align__(16) float g_psum[NG * 128];
__device__ __align__(16) float g_psq[NG * 128];
__device__ __align__(16) float g_scale[128];
__device__ __align__(16) float g_shift[128];
__device__ int g_seg[NG + 1];

// ---------------- helpers ----------------
__device__ __forceinline__ uint32_t smaddr(const void* p) {
    return (uint32_t)__cvta_generic_to_shared(p);
}
__device__ __forceinline__ void cp16(uint32_t d, const void* s, int n) {
    asm volatile("cp.async.ca.shared.global [%0], [%1], 16, %2;\n" :: "r"(d), "l"(s), "r"(n));
}
#define CP_COMMIT() asm volatile("cp.async.commit_group;\n" ::: "memory")
#define CP_WAIT0()  asm volatile("cp.async.wait_group 0;\n" ::: "memory")

__device__ __forceinline__ void mma_bf16(float* d, const uint32_t* a, const uint32_t* b) {
    asm volatile(
        "mma.sync.aligned.m16n8k16.row.col.f32.bf16.bf16.f32 "
        "{%0,%1,%2,%3}, {%4,%5,%6,%7}, {%8,%9}, {%0,%1,%2,%3};"
        : "+f"(d[0]), "+f"(d[1]), "+f"(d[2]), "+f"(d[3])
        : "r"(a[0]), "r"(a[1]), "r"(a[2]), "r"(a[3]), "r"(b[0]), "r"(b[1]));
}
__device__ __forceinline__ void ldsm4(uint32_t* r, uint32_t a) {
    asm volatile("ldmatrix.sync.aligned.m8n8.x4.shared.b16 {%0,%1,%2,%3}, [%4];"
        : "=r"(r[0]), "=r"(r[1]), "=r"(r[2]), "=r"(r[3]) : "r"(a));
}

__device__ __forceinline__ void bsplit2(float a, float b, uint32_t& hi, uint32_t& lo) {
    __nv_bfloat162 h = __floats2bfloat162_rn(a, b);
    hi = *reinterpret_cast<uint32_t*>(&h);
    float ra = a - __bfloat162float(h.x);
    float rb = b - __bfloat162float(h.y);
    __nv_bfloat162 l = __floats2bfloat162_rn(ra, rb);
    lo = *reinterpret_cast<uint32_t*>(&l);
}

// ---- gemm1 smem map (32-row tiles, 256 thr, 2 blocks/SM, Bhi in regs, Blo in smem) ----
#define ROWB 304
#define O1_R1  512                       // staged BH, then A bufs: 2 x 19456 (hi 9728 + lo 9728)
#define O1_BL  (512 + 38912)             // 39424: resident BL
#define O1_RED (O1_BL + 38912)           // 78336: reduction scratch (8KB)
#define SMEM_G1 (O1_RED + 8192)          // 86528 B per block

// ---- gemm2 smem map (32-row tiles, 256 thr, 2 blocks/SM, B in registers) ----
#define ROWB2 272
#define O2_A   512                       // staged B (hi+lo 69632) then A bufs 2 x 17408
#define O2_RED (512 + 34816)             // 35328: reduction scratch (8KB)
#define SMEM_G2 (512 + 69632)            // 70144 B per block (B staging dominates)

// ---------------- K0: segment bounds (batch sorted) ----------------
__global__ void k_bounds(const int* __restrict__ batch, int N) {
    int g = blockIdx.x * blockDim.x + threadIdx.x;
    if (g > NG) return;
    int lo = 0, hi = N;
    while (lo < hi) {
        int mid = (lo + hi) >> 1;
        if (batch[mid] < g) lo = mid + 1; else hi = mid;
    }
    g_seg[g] = lo;
}

// ---------------- K1: per-graph col means of x0 + lam1 = xm @ l1w^T ----------------
__global__ void k_lam1(const float* __restrict__ x, const float* __restrict__ pers0,
                       const float* __restrict__ l1w, int N) {
    __shared__ float s_sum[2][144];
    __shared__ float s_xm[144];
    int g  = blockIdx.x;
    int lo = g_seg[g], hi = g_seg[g + 1];
    int t  = threadIdx.x;
    int phase = t / 144, col = t - phase * 144;

    float acc = 0.f;
    if (col < 128) {
        const float* p = x + col;
        for (int r = lo + phase; r < hi; r += 2) acc += p[(size_t)r * 128];
    } else {
        int j = col - 128;
        int pp = j >> 1, c = j & 1;
        const float* p = pers0 + (size_t)pp * 2 * N + c;
        for (int r = lo + phase; r < hi; r += 2) acc += p[2 * (size_t)r];
    }
    s_sum[phase][col] = acc;
    __syncthreads();
    if (t < 144) {
        float cnt = (float)max(hi - lo, 1);
        s_xm[t] = (s_sum[0][t] + s_sum[1][t]) / cnt;
    }
    __syncthreads();
    if (t < 128) {
        const float* w = l1w + t * 144;
        float a = 0.f;
#pragma unroll 8
        for (int k = 0; k < 144; ++k) a += s_xm[k] * w[k];
        g_lam1[g * 128 + t] = a;
    }
}

// =============== K2: mma.sync GEMM1 (256 thr, 2 blocks/SM): h = relu(x0 @ g1w^T + g1b - lam1[g]) ===============
// 32-row tiles, 8 warps as 1M x 8N (warp: 32 rows x 16 cols). K=144 = 9 k16 steps.
// Bhi in registers; Blo from resident smem. Direct fragment epilogue (no smem roundtrip).
__global__ __launch_bounds__(256, 2) void k_gemm1(
    const float* __restrict__ x, const float* __restrict__ pers0,
    const float* __restrict__ g1w, const float* __restrict__ g1b,
    const float* __restrict__ l2w, int N) {
    extern __shared__ char sm[];
    uint32_t su = smaddr(sm);
    float* sbias = (float*)sm;
    int g  = blockIdx.x;
    int lo = g_seg[g], hi = g_seg[g + 1];
    int tid = threadIdx.x;
    int wid = tid >> 5, l = tid & 31;
    int wn = wid;                              // 1M x 8N
    int seg = l >> 3, l7 = l & 7, gg = l >> 2, tg = l & 3;

    // stage B = g1w as bf16: BH into R1 (temp), BL into resident region
    for (int it = 0; it < 18; ++it) {
        int idx = tid + it * 256;            // [0, 128*36)
        int jr = idx / 36, k4 = idx - jr * 36;
        float4 v = ((const float4*)g1w)[idx];
        uint32_t h01, l01, h23, l23;
        bsplit2(v.x, v.y, h01, l01);
        bsplit2(v.z, v.w, h23, l23);
        int off = jr * ROWB + k4 * 8;
        *(uint2*)(sm + O1_R1 + off) = make_uint2(h01, h23);
        *(uint2*)(sm + O1_BL + off) = make_uint2(l01, l23);
    }
    if (tid < 128) sbias[tid] = g1b[tid] - g_lam1[g * 128 + tid];
    __syncthreads();

    // load Bhi fragments to registers: per warp 16 cols x K=144 = 36 regs
    uint32_t bh[9][4];
    uint32_t blo_off;
    {
        uint32_t bidx = (uint32_t)((wn * 16 + (seg >> 1) * 8 + l7) * ROWB + (seg & 1) * 16);
        uint32_t b_off = su + O1_R1 + bidx;
        blo_off = su + O1_BL + bidx;
#pragma unroll
        for (int ks = 0; ks < 9; ++ks) ldsm4(bh[ks], b_off + ks * 32);
    }
    // per-thread bias for owned cols: col(h,par) = wn*16 + h*8 + 2*tg + par
    float b4[4];
#pragma unroll
    for (int h = 0; h < 2; ++h)
#pragma unroll
        for (int par = 0; par < 2; ++par)
            b4[h * 2 + par] = sbias[wn * 16 + h * 8 + 2 * tg + par];
    __syncthreads();   // BH smem dead; R1 now reused for A buffers

    // register prefetch of one 32-row x0 tile (row = tid>>3, k-eighth = tid&7)
    float4 xv[4]; float2 pv;
    int prow = tid >> 3, pk8 = tid & 7;
    auto loadRegs = [&](int r0i, int rem) {
        int rg = r0i + min(prow, rem - 1);
        const float4* xs = (const float4*)(x + (size_t)rg * 128) + pk8 * 4;
#pragma unroll
        for (int i = 0; i < 4; ++i) xv[i] = xs[i];
        pv = ((const float2*)pers0)[(size_t)pk8 * N + rg];
    };
    auto stsRegs = [&](int buf) {
        char* bhd = sm + O1_R1 + buf * 19456 + prow * ROWB;
        char* bld = bhd + 9728;
#pragma unroll
        for (int i = 0; i < 4; ++i) {
            uint32_t h01, l01, h23, l23;
            bsplit2(xv[i].x, xv[i].y, h01, l01);
            bsplit2(xv[i].z, xv[i].w, h23, l23);
            *(uint2*)(bhd + pk8 * 32 + i * 8) = make_uint2(h01, h23);
            *(uint2*)(bld + pk8 * 32 + i * 8) = make_uint2(l01, l23);
        }
        uint32_t h, lw;
        bsplit2(pv.x, pv.y, h, lw);
        *(uint32_t*)(bhd + 256 + 4 * pk8) = h;
        *(uint32_t*)(bld + 256 + 4 * pk8) = lw;
    };

    float hs4[4] = {0.f, 0.f, 0.f, 0.f};

    uint32_t a_off = su + O1_R1 + (uint32_t)(((seg & 1) * 8 + l7) * ROWB + (seg >> 1) * 16);
    int colbase = wn * 16 + 2 * tg;

    if (lo < hi) { loadRegs(lo, min(32, hi - lo)); stsRegs(0); }
    __syncthreads();

    int t = 0;
    for (int r0 = lo; r0 < hi; r0 += 32, ++t) {
        int buf = t & 1;
        int nr0 = r0 + 32;
        bool havnext = nr0 < hi;
        if (havnext) loadRegs(nr0, min(32, hi - nr0));

        float D[4][4];
#pragma unroll
        for (int i = 0; i < 4; ++i)
#pragma unroll
            for (int q = 0; q < 4; ++q) D[i][q] = 0.f;

        uint32_t abase = a_off + buf * 19456;
#pragma unroll
        for (int ks = 0; ks < 9; ++ks) {
            uint32_t ah0[4], al0[4], ah1[4], al1[4], blo[4];
            ldsm4(ah0, abase + ks * 32);
            ldsm4(al0, abase + 9728 + ks * 32);
            ldsm4(ah1, abase + 16 * ROWB + ks * 32);
            ldsm4(al1, abase + 16 * ROWB + 9728 + ks * 32);
            ldsm4(blo, blo_off + ks * 32);
            mma_bf16(D[0], ah0, bh[ks]);   mma_bf16(D[1], ah0, bh[ks] + 2);
            mma_bf16(D[0], ah0, blo);      mma_bf16(D[1], ah0, blo + 2);
            mma_bf16(D[0], al0, bh[ks]);   mma_bf16(D[1], al0, bh[ks] + 2);
            mma_bf16(D[2], ah1, bh[ks]);   mma_bf16(D[3], ah1, bh[ks] + 2);
            mma_bf16(D[2], ah1, blo);      mma_bf16(D[3], ah1, blo + 2);
            mma_bf16(D[2], al1, bh[ks]);   mma_bf16(D[3], al1, bh[ks] + 2);
        }
        if (havnext) stsRegs(buf ^ 1);

        // direct fragment epilogue: relu + col sums + bf16 hi/lo STG
#pragma unroll
        for (int m = 0; m < 2; ++m) {
            int rA = r0 + m * 16 + gg;
#pragma unroll
            for (int h = 0; h < 2; ++h) {
                float* d = D[m * 2 + h];
                int col = colbase + h * 8;
                if (rA < hi) {
                    float va = fmaxf(d[0] + b4[h * 2 + 0], 0.f);
                    float vb = fmaxf(d[1] + b4[h * 2 + 1], 0.f);
                    hs4[h * 2 + 0] += va; hs4[h * 2 + 1] += vb;
                    uint32_t hhh, lll;
                    bsplit2(va, vb, hhh, lll);
                    size_t off = (size_t)rA * 128 + col;
                    *(uint32_t*)(g_hhi + off) = hhh;
                    *(uint32_t*)(g_hlo + off) = lll;
                }
                if (rA + 8 < hi) {
                    float va = fmaxf(d[2] + b4[h * 2 + 0], 0.f);
                    float vb = fmaxf(d[3] + b4[h * 2 + 1], 0.f);
                    hs4[h * 2 + 0] += va; hs4[h * 2 + 1] += vb;
                    uint32_t hhh, lll;
                    bsplit2(va, vb, hhh, lll);
                    size_t off = (size_t)(rA + 8) * 128 + col;
                    *(uint32_t*)(g_hhi + off) = hhh;
                    *(uint32_t*)(g_hlo + off) = lll;
                }
            }
        }
        __syncthreads();
    }

    // deterministic col-sum reduce -> hm -> lam2 = hm @ l2w^T
    float* red = (float*)(sm + O1_RED);
    __syncthreads();
#pragma unroll
    for (int i = 0; i < 4; ++i) red[tid * 4 + i] = hs4[i];
    __syncthreads();
    if (tid < 128) {
        int c = tid;
        int wn_ = c >> 4, cc = c & 15;
        int tg_ = (cc & 7) >> 1, s = ((cc >> 3) << 1) + (cc & 1);
        float ssum = 0.f;
#pragma unroll
        for (int gg_ = 0; gg_ < 8; ++gg_)
            ssum += red[(wn_ * 32 + gg_ * 4 + tg_) * 4 + s];
        float cnt = (float)max(hi - lo, 1);
        red[1024 + c] = ssum / cnt;
    }
    __syncthreads();
    if (tid < 128) {
        const float* w = l2w + tid * 128;
        const float* hm = red + 1024;
        float a = 0.f;
#pragma unroll 8
        for (int k = 0; k < 128; ++k) a += hm[k] * w[k];
        g_lam2[g * 128 + tid] = a;
    }
}

// =============== K4: mma.sync GEMM2 (256 thr, 2 blocks/SM): y0 = h @ g2w^T + g2b - lam2[g] ===============
// 32-row tiles, 8 warps as 1M x 8N. B in registers. Direct fragment epilogue.
__global__ __launch_bounds__(256, 2) void k_gemm2(
    const float* __restrict__ g2w, const float* __restrict__ g2b, int N) {
    extern __shared__ char sm[];
    uint32_t su = smaddr(sm);
    float* sbias = (float*)sm;
    int g  = blockIdx.x;
    int lo = g_seg[g], hi = g_seg[g + 1];
    int tid = threadIdx.x;
    int wid = tid >> 5, l = tid & 31;
    int wn = wid;                              // 1M x 8N
    int seg = l >> 3, l7 = l & 7, gg = l >> 2, tg = l & 3;

    // stage B = g2w bf16 hi/lo into smem once (hi at 512, lo at 512+34816)
    for (int it = 0; it < 16; ++it) {
        int idx = tid + it * 256;            // [0, 128*32)
        int jr = idx >> 5, k4 = idx & 31;
        float4 v = ((const float4*)g2w)[idx];
        uint32_t h01, l01, h23, l23;
        bsplit2(v.x, v.y, h01, l01);
        bsplit2(v.z, v.w, h23, l23);
        int off = jr * ROWB2 + k4 * 8;
        *(uint2*)(sm + 512 + off)         = make_uint2(h01, h23);
        *(uint2*)(sm + 512 + 34816 + off) = make_uint2(l01, l23);
    }
    if (tid < 128) sbias[tid] = g2b[tid] - g_lam2[g * 128 + tid];
    __syncthreads();

    // load B fragments to registers: per warp 16 cols x K=128, hi+lo = 64 regs
    uint32_t bh[8][4], bl[8][4];
    {
        uint32_t b_off = su + 512 + (uint32_t)((wn * 16 + (seg >> 1) * 8 + l7) * ROWB2 + (seg & 1) * 16);
#pragma unroll
        for (int ks = 0; ks < 8; ++ks) {
            ldsm4(bh[ks], b_off + ks * 32);
            ldsm4(bl[ks], b_off + 34816 + ks * 32);
        }
    }
    float b4[4];
#pragma unroll
    for (int h = 0; h < 2; ++h)
#pragma unroll
        for (int par = 0; par < 2; ++par)
            b4[h * 2 + par] = sbias[wn * 16 + h * 8 + 2 * tg + par];
    __syncthreads();   // B smem dead; region now reused for A buffers

    // A staging via cp.async from pre-split h arrays (32 rows per tile)
    auto stageA = [&](int r0i, int rem, int buf) {
#pragma unroll
        for (int hl = 0; hl < 2; ++hl) {
            const __nv_bfloat16* src = hl ? g_hlo : g_hhi;
            uint32_t base = su + O2_A + buf * 17408 + hl * 8704;
#pragma unroll
            for (int it = 0; it < 2; ++it) {
                int idx = tid + it * 256;        // [0, 32*16)
                int r = idx >> 4, u = idx & 15;
                int rc = (r < rem) ? r : 0;
                cp16(base + r * ROWB2 + u * 16,
                     src + (size_t)(r0i + rc) * 128 + u * 8, (r < rem) ? 16 : 0);
            }
        }
    };

    float sD[4] = {0.f, 0.f, 0.f, 0.f}, sQ[4] = {0.f, 0.f, 0.f, 0.f};

    uint32_t a_off = su + O2_A + (uint32_t)(((seg & 1) * 8 + l7) * ROWB2 + (seg >> 1) * 16);
    int colbase = wn * 16 + 2 * tg;

    if (lo < hi) { stageA(lo, min(32, hi - lo), 0); CP_COMMIT(); CP_WAIT0(); }
    __syncthreads();

    int t = 0;
    for (int r0 = lo; r0 < hi; r0 += 32, ++t) {
        int buf = t & 1;
        int nr0 = r0 + 32;
        bool havnext = nr0 < hi;
        if (havnext) { stageA(nr0, min(32, hi - nr0), buf ^ 1); CP_COMMIT(); }

        float D[4][4];
#pragma unroll
        for (int i = 0; i < 4; ++i)
#pragma unroll
            for (int q = 0; q < 4; ++q) D[i][q] = 0.f;

        uint32_t abase = a_off + buf * 17408;
#pragma unroll
        for (int ks = 0; ks < 8; ++ks) {
            uint32_t ah0[4], al0[4], ah1[4], al1[4];
            ldsm4(ah0, abase + ks * 32);
            ldsm4(al0, abase + 8704 + ks * 32);
            ldsm4(ah1, abase + 16 * ROWB2 + ks * 32);
            ldsm4(al1, abase + 16 * ROWB2 + 8704 + ks * 32);
            mma_bf16(D[0], ah0, bh[ks]);     mma_bf16(D[1], ah0, bh[ks] + 2);
            mma_bf16(D[0], ah0, bl[ks]);     mma_bf16(D[1], ah0, bl[ks] + 2);
            mma_bf16(D[0], al0, bh[ks]);     mma_bf16(D[1], al0, bh[ks] + 2);
            mma_bf16(D[2], ah1, bh[ks]);     mma_bf16(D[3], ah1, bh[ks] + 2);
            mma_bf16(D[2], ah1, bl[ks]);     mma_bf16(D[3], ah1, bl[ks] + 2);
            mma_bf16(D[2], al1, bh[ks]);     mma_bf16(D[3], al1, bh[ks] + 2);
        }

        // direct fragment epilogue: raw sums + biased y STG (32B-sector aligned float2)
#pragma unroll
        for (int m = 0; m < 2; ++m) {
            int rA = r0 + m * 16 + gg;
#pragma unroll
            for (int h = 0; h < 2; ++h) {
                float* d = D[m * 2 + h];
                int col = colbase + h * 8;
                if (rA < hi) {
                    sD[h * 2 + 0] += d[0]; sQ[h * 2 + 0] += d[0] * d[0];
                    sD[h * 2 + 1] += d[1]; sQ[h * 2 + 1] += d[1] * d[1];
                    *(float2*)(g_y + (size_t)rA * 128 + col) =
                        make_float2(d[0] + b4[h * 2 + 0], d[1] + b4[h * 2 + 1]);
                }
                if (rA + 8 < hi) {
                    sD[h * 2 + 0] += d[2]; sQ[h * 2 + 0] += d[2] * d[2];
                    sD[h * 2 + 1] += d[3]; sQ[h * 2 + 1] += d[3] * d[3];
                    *(float2*)(g_y + (size_t)(rA + 8) * 128 + col) =
                        make_float2(d[2] + b4[h * 2 + 0], d[3] + b4[h * 2 + 1]);
                }
            }
        }
        if (havnext) CP_WAIT0();
        __syncthreads();
    }

    // deterministic BN partials: fixed-order reduce of raw sums + analytic bias fixup
    float* red = (float*)(sm + O2_RED);
    __syncthreads();
#pragma unroll
    for (int i = 0; i < 4; ++i) { red[tid * 8 + i] = sD[i]; red[tid * 8 + 4 + i] = sQ[i]; }
    __syncthreads();
    if (tid < 128) {
        int c = tid;
        int wn_ = c >> 4, cc = c & 15;
        int tg_ = (cc & 7) >> 1, s = ((cc >> 3) << 1) + (cc & 1);
        float sum = 0.f, sq = 0.f;
#pragma unroll
        for (int gg_ = 0; gg_ < 8; ++gg_) {
            int tt = wn_ * 32 + gg_ * 4 + tg_;
            sum += red[tt * 8 + s];
            sq  += red[tt * 8 + 4 + s];
        }
        float b = sbias[c];
        float cnt = (float)(hi - lo);
        g_psum[g * 128 + c] = sum + cnt * b;
        g_psq[g * 128 + c]  = sq + 2.f * b * sum + cnt * b * b;
    }
}

// ---------------- K5: BN stats -> scale/shift ----------------
__global__ void k_stats(const float* __restrict__ bn_g, const float* __restrict__ bn_b, int N) {
    int t = threadIdx.x;  // 128
    float s = 0.f, q = 0.f;
    for (int g = 0; g < NG; ++g) {
        s += g_psum[g * 128 + t];
        q += g_psq[g * 128 + t];
    }
    float invN = 1.f / (float)N;
    float mu  = s * invN;
    float var = fmaxf(q * invN - mu * mu, 0.f);
    float sc  = rsqrtf(var + BN_EPS) * bn_g[t];
    g_scale[t] = sc;
    g_shift[t] = bn_b[t] - mu * sc;
}

// ---------------- K6: out = x + y0*scale + shift ----------------
__global__ void k_out(const float* __restrict__ x, float* __restrict__ out, int total4) {
    int i = blockIdx.x * blockDim.x + threadIdx.x;
    if (i >= total4) return;
    int j4 = i & 31;
    float4 sc = ((const float4*)g_scale)[j4];
    float4 sh = ((const float4*)g_shift)[j4];
    float4 xv = ((const float4*)x)[i];
    float4 yv = ((const float4*)g_y)[i];
    float4 o;
    o.x = xv.x + yv.x * sc.x + sh.x;
    o.y = xv.y + yv.y * sc.y + sh.y;
    o.z = xv.z + yv.z * sc.z + sh.z;
    o.w = xv.w + yv.w * sc.w + sh.w;
    ((float4*)out)[i] = o;
}

// ---------------- launch ----------------
extern "C" void kernel_launch(void* const* d_in, const int* in_sizes, int n_in,
                              void* d_out, int out_size) {
    const float* x     = (const float*)d_in[0];
    const int*   batch = (const int*)d_in[1];
    const float* pers0 = (const float*)d_in[2];
    const float* g1w   = (const float*)d_in[3];
    const float* g1b   = (const float*)d_in[4];
    const float* l1w   = (const float*)d_in[5];
    const float* g2w   = (const float*)d_in[6];
    const float* g2b   = (const float*)d_in[7];
    const float* l2w   = (const float*)d_in[8];
    const float* bng   = (const float*)d_in[9];
    const float* bnb   = (const float*)d_in[10];
    float* out = (float*)d_out;
    int N = in_sizes[0] / 128;

    cudaFuncSetAttribute(k_gemm1, cudaFuncAttributeMaxDynamicSharedMemorySize, SMEM_G1);
    cudaFuncSetAttribute(k_gemm2, cudaFuncAttributeMaxDynamicSharedMemorySize, SMEM_G2);

    k_bounds<<<(NG + 256) / 256, 256>>>(batch, N);
    k_lam1<<<NG, 288>>>(x, pers0, l1w, N);
    k_gemm1<<<NG, 256, SMEM_G1>>>(x, pers0, g1w, g1b, l2w, N);
    k_gemm2<<<NG, 256, SMEM_G2>>>(g2w, g2b, N);
    k_stats<<<1, 128>>>(bng, bnb, N);
    int total4 = N * 32;
    k_out<<<(total4 + 255) / 256, 256>>>(x, out, total4);
}

// round 17
// speedup vs baseline: 1.2755x; 1.0027x over previous
#include <cuda_runtime.h>
#include <cuda_bf16.h>
#include <cstdint>

#define NG   2048
#define MAXN 500000
#define BN_EPS 1e-5f

typedef unsigned long long ull;

// ---------------- scratch (device globals; no allocation allowed) ----------------
__device__ __align__(16) __nv_bfloat16 g_hhi[(size_t)MAXN * 128];
__device__ __align__(16) __nv_bfloat16 g_hlo[(size_t)MAXN * 128];
__device__ __align__(16) float g_y[(size_t)MAXN * 128];
__device__ __align__(16) float g_lam1[NG * 128];
__device__ __align__(16) float g_lam2[NG * 128];
__device__ __align__(16) float g_psum[NG * 128];
__device__ __align__(16) float g_psq[NG * 128];
__device__ __align__(16) float g_scale[128];
__device__ __align__(16) float g_shift[128];
__device__ int g_seg[NG + 1];

// ---------------- helpers ----------------
__device__ __forceinline__ uint32_t smaddr(const void* p) {
    return (uint32_t)__cvta_generic_to_shared(p);
}
__device__ __forceinline__ void cp16(uint32_t d, const void* s, int n) {
    asm volatile("cp.async.ca.shared.global [%0], [%1], 16, %2;\n" :: "r"(d), "l"(s), "r"(n));
}
#define CP_COMMIT() asm volatile("cp.async.commit_group;\n" ::: "memory")
#define CP_WAIT0()  asm volatile("cp.async.wait_group 0;\n" ::: "memory")

__device__ __forceinline__ void mma_bf16(float* d, const uint32_t* a, const uint32_t* b) {
    asm volatile(
        "mma.sync.aligned.m16n8k16.row.col.f32.bf16.bf16.f32 "
        "{%0,%1,%2,%3}, {%4,%5,%6,%7}, {%8,%9}, {%0,%1,%2,%3};"
        : "+f"(d[0]), "+f"(d[1]), "+f"(d[2]), "+f"(d[3])
        : "r"(a[0]), "r"(a[1]), "r"(a[2]), "r"(a[3]), "r"(b[0]), "r"(b[1]));
}
__device__ __forceinline__ void ldsm4(uint32_t* r, uint32_t a) {
    asm volatile("ldmatrix.sync.aligned.m8n8.x4.shared.b16 {%0,%1,%2,%3}, [%4];"
        : "=r"(r[0]), "=r"(r[1]), "=r"(r[2]), "=r"(r[3]) : "r"(a));
}

__device__ __forceinline__ void bsplit2(float a, float b, uint32_t& hi, uint32_t& lo) {
    __nv_bfloat162 h = __floats2bfloat162_rn(a, b);
    hi = *reinterpret_cast<uint32_t*>(&h);
    float ra = a - __bfloat162float(h.x);
    float rb = b - __bfloat162float(h.y);
    __nv_bfloat162 l = __floats2bfloat162_rn(ra, rb);
    lo = *reinterpret_cast<uint32_t*>(&l);
}

// ---- gemm1 smem map (32-row tiles, 256 thr, 2 blocks/SM, Bhi in regs, Blo in smem) ----
#define ROWB 304
#define O1_R1  512                       // staged BH, then A bufs: 2 x 19456 (hi 9728 + lo 9728)
#define O1_BL  (512 + 38912)             // 39424: resident BL
#define O1_RED (O1_BL + 38912)           // 78336: reduction scratch (8KB)
#define SMEM_G1 (O1_RED + 8192)          // 86528 B per block

// ---- gemm2 smem map (32-row tiles, 256 thr, 2 blocks/SM, B in registers) ----
#define ROWB2 272
#define O2_A   512                       // staged B (hi+lo 69632) then A bufs 2 x 17408
#define O2_RED (512 + 34816)             // 35328: reduction scratch (8KB)
#define SMEM_G2 (512 + 69632)            // 70144 B per block (B staging dominates)

// ---------------- K0: segment bounds (batch sorted) ----------------
__global__ void k_bounds(const int* __restrict__ batch, int N) {
    int g = blockIdx.x * blockDim.x + threadIdx.x;
    if (g > NG) return;
    int lo = 0, hi = N;
    while (lo < hi) {
        int mid = (lo + hi) >> 1;
        if (batch[mid] < g) lo = mid + 1; else hi = mid;
    }
    g_seg[g] = lo;
}

// ---------------- K1: per-graph col means of x0 + lam1 = xm @ l1w^T ----------------
__global__ void k_lam1(const float* __restrict__ x, const float* __restrict__ pers0,
                       const float* __restrict__ l1w, int N) {
    __shared__ float s_sum[2][144];
    __shared__ float s_xm[144];
    int g  = blockIdx.x;
    int lo = g_seg[g], hi = g_seg[g + 1];
    int t  = threadIdx.x;
    int phase = t / 144, col = t - phase * 144;

    float acc = 0.f;
    if (col < 128) {
        const float* p = x + col;
        for (int r = lo + phase; r < hi; r += 2) acc += p[(size_t)r * 128];
    } else {
        int j = col - 128;
        int pp = j >> 1, c = j & 1;
        const float* p = pers0 + (size_t)pp * 2 * N + c;
        for (int r = lo + phase; r < hi; r += 2) acc += p[2 * (size_t)r];
    }
    s_sum[phase][col] = acc;
    __syncthreads();
    if (t < 144) {
        float cnt = (float)max(hi - lo, 1);
        s_xm[t] = (s_sum[0][t] + s_sum[1][t]) / cnt;
    }
    __syncthreads();
    if (t < 128) {
        const float* w = l1w + t * 144;
        float a = 0.f;
#pragma unroll 8
        for (int k = 0; k < 144; ++k) a += s_xm[k] * w[k];
        g_lam1[g * 128 + t] = a;
    }
}

// =============== K2: mma.sync GEMM1 (256 thr, 2 blocks/SM): h = relu(x0 @ g1w^T + g1b - lam1[g]) ===============
// REVERSED graph order: first wave reads x tail still L2-resident from k_lam1;
// finishes writing low-g h last so gemm2 (forward) hits it in L2.
__global__ __launch_bounds__(256, 2) void k_gemm1(
    const float* __restrict__ x, const float* __restrict__ pers0,
    const float* __restrict__ g1w, const float* __restrict__ g1b,
    const float* __restrict__ l2w, int N) {
    extern __shared__ char sm[];
    uint32_t su = smaddr(sm);
    float* sbias = (float*)sm;
    int g  = NG - 1 - blockIdx.x;
    int lo = g_seg[g], hi = g_seg[g + 1];
    int tid = threadIdx.x;
    int wid = tid >> 5, l = tid & 31;
    int wn = wid;                              // 1M x 8N
    int seg = l >> 3, l7 = l & 7, gg = l >> 2, tg = l & 3;

    // stage B = g1w as bf16: BH into R1 (temp), BL into resident region
    for (int it = 0; it < 18; ++it) {
        int idx = tid + it * 256;            // [0, 128*36)
        int jr = idx / 36, k4 = idx - jr * 36;
        float4 v = ((const float4*)g1w)[idx];
        uint32_t h01, l01, h23, l23;
        bsplit2(v.x, v.y, h01, l01);
        bsplit2(v.z, v.w, h23, l23);
        int off = jr * ROWB + k4 * 8;
        *(uint2*)(sm + O1_R1 + off) = make_uint2(h01, h23);
        *(uint2*)(sm + O1_BL + off) = make_uint2(l01, l23);
    }
    if (tid < 128) sbias[tid] = g1b[tid] - g_lam1[g * 128 + tid];
    __syncthreads();

    // load Bhi fragments to registers: per warp 16 cols x K=144 = 36 regs
    uint32_t bh[9][4];
    uint32_t blo_off;
    {
        uint32_t bidx = (uint32_t)((wn * 16 + (seg >> 1) * 8 + l7) * ROWB + (seg & 1) * 16);
        uint32_t b_off = su + O1_R1 + bidx;
        blo_off = su + O1_BL + bidx;
#pragma unroll
        for (int ks = 0; ks < 9; ++ks) ldsm4(bh[ks], b_off + ks * 32);
    }
    // per-thread bias for owned cols: col(h,par) = wn*16 + h*8 + 2*tg + par
    float b4[4];
#pragma unroll
    for (int h = 0; h < 2; ++h)
#pragma unroll
        for (int par = 0; par < 2; ++par)
            b4[h * 2 + par] = sbias[wn * 16 + h * 8 + 2 * tg + par];
    __syncthreads();   // BH smem dead; R1 now reused for A buffers

    // register prefetch of one 32-row x0 tile (row = tid>>3, k-eighth = tid&7)
    float4 xv[4]; float2 pv;
    int prow = tid >> 3, pk8 = tid & 7;
    auto loadRegs = [&](int r0i, int rem) {
        int rg = r0i + min(prow, rem - 1);
        const float4* xs = (const float4*)(x + (size_t)rg * 128) + pk8 * 4;
#pragma unroll
        for (int i = 0; i < 4; ++i) xv[i] = xs[i];
        pv = ((const float2*)pers0)[(size_t)pk8 * N + rg];
    };
    auto stsRegs = [&](int buf) {
        char* bhd = sm + O1_R1 + buf * 19456 + prow * ROWB;
        char* bld = bhd + 9728;
#pragma unroll
        for (int i = 0; i < 4; ++i) {
            uint32_t h01, l01, h23, l23;
            bsplit2(xv[i].x, xv[i].y, h01, l01);
            bsplit2(xv[i].z, xv[i].w, h23, l23);
            *(uint2*)(bhd + pk8 * 32 + i * 8) = make_uint2(h01, h23);
            *(uint2*)(bld + pk8 * 32 + i * 8) = make_uint2(l01, l23);
        }
        uint32_t h, lw;
        bsplit2(pv.x, pv.y, h, lw);
        *(uint32_t*)(bhd + 256 + 4 * pk8) = h;
        *(uint32_t*)(bld + 256 + 4 * pk8) = lw;
    };

    float hs4[4] = {0.f, 0.f, 0.f, 0.f};

    uint32_t a_off = su + O1_R1 + (uint32_t)(((seg & 1) * 8 + l7) * ROWB + (seg >> 1) * 16);
    int colbase = wn * 16 + 2 * tg;

    if (lo < hi) { loadRegs(lo, min(32, hi - lo)); stsRegs(0); }
    __syncthreads();

    int t = 0;
    for (int r0 = lo; r0 < hi; r0 += 32, ++t) {
        int buf = t & 1;
        int nr0 = r0 + 32;
        bool havnext = nr0 < hi;
        if (havnext) loadRegs(nr0, min(32, hi - nr0));

        float D[4][4];
#pragma unroll
        for (int i = 0; i < 4; ++i)
#pragma unroll
            for (int q = 0; q < 4; ++q) D[i][q] = 0.f;

        uint32_t abase = a_off + buf * 19456;
#pragma unroll
        for (int ks = 0; ks < 9; ++ks) {
            uint32_t ah0[4], al0[4], ah1[4], al1[4], blo[4];
            ldsm4(ah0, abase + ks * 32);
            ldsm4(al0, abase + 9728 + ks * 32);
            ldsm4(ah1, abase + 16 * ROWB + ks * 32);
            ldsm4(al1, abase + 16 * ROWB + 9728 + ks * 32);
            ldsm4(blo, blo_off + ks * 32);
            mma_bf16(D[0], ah0, bh[ks]);   mma_bf16(D[1], ah0, bh[ks] + 2);
            mma_bf16(D[0], ah0, blo);      mma_bf16(D[1], ah0, blo + 2);
            mma_bf16(D[0], al0, bh[ks]);   mma_bf16(D[1], al0, bh[ks] + 2);
            mma_bf16(D[2], ah1, bh[ks]);   mma_bf16(D[3], ah1, bh[ks] + 2);
            mma_bf16(D[2], ah1, blo);      mma_bf16(D[3], ah1, blo + 2);
            mma_bf16(D[2], al1, bh[ks]);   mma_bf16(D[3], al1, bh[ks] + 2);
        }
        if (havnext) stsRegs(buf ^ 1);

        // direct fragment epilogue: relu + col sums + bf16 hi/lo STG
#pragma unroll
        for (int m = 0; m < 2; ++m) {
            int rA = r0 + m * 16 + gg;
#pragma unroll
            for (int h = 0; h < 2; ++h) {
                float* d = D[m * 2 + h];
                int col = colbase + h * 8;
                if (rA < hi) {
                    float va = fmaxf(d[0] + b4[h * 2 + 0], 0.f);
                    float vb = fmaxf(d[1] + b4[h * 2 + 1], 0.f);
                    hs4[h * 2 + 0] += va; hs4[h * 2 + 1] += vb;
                    uint32_t hhh, lll;
                    bsplit2(va, vb, hhh, lll);
                    size_t off = (size_t)rA * 128 + col;
                    *(uint32_t*)(g_hhi + off) = hhh;
                    *(uint32_t*)(g_hlo + off) = lll;
                }
                if (rA + 8 < hi) {
                    float va = fmaxf(d[2] + b4[h * 2 + 0], 0.f);
                    float vb = fmaxf(d[3] + b4[h * 2 + 1], 0.f);
                    hs4[h * 2 + 0] += va; hs4[h * 2 + 1] += vb;
                    uint32_t hhh, lll;
                    bsplit2(va, vb, hhh, lll);
                    size_t off = (size_t)(rA + 8) * 128 + col;
                    *(uint32_t*)(g_hhi + off) = hhh;
                    *(uint32_t*)(g_hlo + off) = lll;
                }
            }
        }
        __syncthreads();
    }

    // deterministic col-sum reduce -> hm -> lam2 = hm @ l2w^T
    float* red = (float*)(sm + O1_RED);
    __syncthreads();
#pragma unroll
    for (int i = 0; i < 4; ++i) red[tid * 4 + i] = hs4[i];
    __syncthreads();
    if (tid < 128) {
        int c = tid;
        int wn_ = c >> 4, cc = c & 15;
        int tg_ = (cc & 7) >> 1, s = ((cc >> 3) << 1) + (cc & 1);
        float ssum = 0.f;
#pragma unroll
        for (int gg_ = 0; gg_ < 8; ++gg_)
            ssum += red[(wn_ * 32 + gg_ * 4 + tg_) * 4 + s];
        float cnt = (float)max(hi - lo, 1);
        red[1024 + c] = ssum / cnt;
    }
    __syncthreads();
    if (tid < 128) {
        const float* w = l2w + tid * 128;
        const float* hm = red + 1024;
        float a = 0.f;
#pragma unroll 8
        for (int k = 0; k < 128; ++k) a += hm[k] * w[k];
        g_lam2[g * 128 + tid] = a;
    }
}

// =============== K4: mma.sync GEMM2 (256 thr, 2 blocks/SM): y0 = h @ g2w^T + g2b - lam2[g] ===============
// FORWARD order: first wave reads low-g h, freshly L2-resident from reversed gemm1.
__global__ __launch_bounds__(256, 2) void k_gemm2(
    const float* __restrict__ g2w, const float* __restrict__ g2b, int N) {
    extern __shared__ char sm[];
    uint32_t su = smaddr(sm);
    float* sbias = (float*)sm;
    int g  = blockIdx.x;
    int lo = g_seg[g], hi = g_seg[g + 1];
    int tid = threadIdx.x;
    int wid = tid >> 5, l = tid & 31;
    int wn = wid;                              // 1M x 8N
    int seg = l >> 3, l7 = l & 7, gg = l >> 2, tg = l & 3;

    // stage B = g2w bf16 hi/lo into smem once (hi at 512, lo at 512+34816)
    for (int it = 0; it < 16; ++it) {
        int idx = tid + it * 256;            // [0, 128*32)
        int jr = idx >> 5, k4 = idx & 31;
        float4 v = ((const float4*)g2w)[idx];
        uint32_t h01, l01, h23, l23;
        bsplit2(v.x, v.y, h01, l01);
        bsplit2(v.z, v.w, h23, l23);
        int off = jr * ROWB2 + k4 * 8;
        *(uint2*)(sm + 512 + off)         = make_uint2(h01, h23);
        *(uint2*)(sm + 512 + 34816 + off) = make_uint2(l01, l23);
    }
    if (tid < 128) sbias[tid] = g2b[tid] - g_lam2[g * 128 + tid];
    __syncthreads();

    // load B fragments to registers: per warp 16 cols x K=128, hi+lo = 64 regs
    uint32_t bh[8][4], bl[8][4];
    {
        uint32_t b_off = su + 512 + (uint32_t)((wn * 16 + (seg >> 1) * 8 + l7) * ROWB2 + (seg & 1) * 16);
#pragma unroll
        for (int ks = 0; ks < 8; ++ks) {
            ldsm4(bh[ks], b_off + ks * 32);
            ldsm4(bl[ks], b_off + 34816 + ks * 32);
        }
    }
    float b4[4];
#pragma unroll
    for (int h = 0; h < 2; ++h)
#pragma unroll
        for (int par = 0; par < 2; ++par)
            b4[h * 2 + par] = sbias[wn * 16 + h * 8 + 2 * tg + par];
    __syncthreads();   // B smem dead; region now reused for A buffers

    // A staging via cp.async from pre-split h arrays (32 rows per tile)
    auto stageA = [&](int r0i, int rem, int buf) {
#pragma unroll
        for (int hl = 0; hl < 2; ++hl) {
            const __nv_bfloat16* src = hl ? g_hlo : g_hhi;
            uint32_t base = su + O2_A + buf * 17408 + hl * 8704;
#pragma unroll
            for (int it = 0; it < 2; ++it) {
                int idx = tid + it * 256;        // [0, 32*16)
                int r = idx >> 4, u = idx & 15;
                int rc = (r < rem) ? r : 0;
                cp16(base + r * ROWB2 + u * 16,
                     src + (size_t)(r0i + rc) * 128 + u * 8, (r < rem) ? 16 : 0);
            }
        }
    };

    float sD[4] = {0.f, 0.f, 0.f, 0.f}, sQ[4] = {0.f, 0.f, 0.f, 0.f};

    uint32_t a_off = su + O2_A + (uint32_t)(((seg & 1) * 8 + l7) * ROWB2 + (seg >> 1) * 16);
    int colbase = wn * 16 + 2 * tg;

    if (lo < hi) { stageA(lo, min(32, hi - lo), 0); CP_COMMIT(); CP_WAIT0(); }
    __syncthreads();

    int t = 0;
    for (int r0 = lo; r0 < hi; r0 += 32, ++t) {
        int buf = t & 1;
        int nr0 = r0 + 32;
        bool havnext = nr0 < hi;
        if (havnext) { stageA(nr0, min(32, hi - nr0), buf ^ 1); CP_COMMIT(); }

        float D[4][4];
#pragma unroll
        for (int i = 0; i < 4; ++i)
#pragma unroll
            for (int q = 0; q < 4; ++q) D[i][q] = 0.f;

        uint32_t abase = a_off + buf * 17408;
#pragma unroll
        for (int ks = 0; ks < 8; ++ks) {
            uint32_t ah0[4], al0[4], ah1[4], al1[4];
            ldsm4(ah0, abase + ks * 32);
            ldsm4(al0, abase + 8704 + ks * 32);
            ldsm4(ah1, abase + 16 * ROWB2 + ks * 32);
            ldsm4(al1, abase + 16 * ROWB2 + 8704 + ks * 32);
            mma_bf16(D[0], ah0, bh[ks]);     mma_bf16(D[1], ah0, bh[ks] + 2);
            mma_bf16(D[0], ah0, bl[ks]);     mma_bf16(D[1], ah0, bl[ks] + 2);
            mma_bf16(D[0], al0, bh[ks]);     mma_bf16(D[1], al0, bh[ks] + 2);
            mma_bf16(D[2], ah1, bh[ks]);     mma_bf16(D[3], ah1, bh[ks] + 2);
            mma_bf16(D[2], ah1, bl[ks]);     mma_bf16(D[3], ah1, bl[ks] + 2);
            mma_bf16(D[2], al1, bh[ks]);     mma_bf16(D[3], al1, bh[ks] + 2);
        }

        // direct fragment epilogue: raw sums + biased y STG (32B-sector aligned float2)
#pragma unroll
        for (int m = 0; m < 2; ++m) {
            int rA = r0 + m * 16 + gg;
#pragma unroll
            for (int h = 0; h < 2; ++h) {
                float* d = D[m * 2 + h];
                int col = colbase + h * 8;
                if (rA < hi) {
                    sD[h * 2 + 0] += d[0]; sQ[h * 2 + 0] += d[0] * d[0];
                    sD[h * 2 + 1] += d[1]; sQ[h * 2 + 1] += d[1] * d[1];
                    *(float2*)(g_y + (size_t)rA * 128 + col) =
                        make_float2(d[0] + b4[h * 2 + 0], d[1] + b4[h * 2 + 1]);
                }
                if (rA + 8 < hi) {
                    sD[h * 2 + 0] += d[2]; sQ[h * 2 + 0] += d[2] * d[2];
                    sD[h * 2 + 1] += d[3]; sQ[h * 2 + 1] += d[3] * d[3];
                    *(float2*)(g_y + (size_t)(rA + 8) * 128 + col) =
                        make_float2(d[2] + b4[h * 2 + 0], d[3] + b4[h * 2 + 1]);
                }
            }
        }
        if (havnext) CP_WAIT0();
        __syncthreads();
    }

    // deterministic BN partials: fixed-order reduce of raw sums + analytic bias fixup
    float* red = (float*)(sm + O2_RED);
    __syncthreads();
#pragma unroll
    for (int i = 0; i < 4; ++i) { red[tid * 8 + i] = sD[i]; red[tid * 8 + 4 + i] = sQ[i]; }
    __syncthreads();
    if (tid < 128) {
        int c = tid;
        int wn_ = c >> 4, cc = c & 15;
        int tg_ = (cc & 7) >> 1, s = ((cc >> 3) << 1) + (cc & 1);
        float sum = 0.f, sq = 0.f;
#pragma unroll
        for (int gg_ = 0; gg_ < 8; ++gg_) {
            int tt = wn_ * 32 + gg_ * 4 + tg_;
            sum += red[tt * 8 + s];
            sq  += red[tt * 8 + 4 + s];
        }
        float b = sbias[c];
        float cnt = (float)(hi - lo);
        g_psum[g * 128 + c] = sum + cnt * b;
        g_psq[g * 128 + c]  = sq + 2.f * b * sum + cnt * b * b;
    }
}

// ---------------- K5: BN stats -> scale/shift ----------------
__global__ void k_stats(const float* __restrict__ bn_g, const float* __restrict__ bn_b, int N) {
    int t = threadIdx.x;  // 128
    float s = 0.f, q = 0.f;
    for (int g = 0; g < NG; ++g) {
        s += g_psum[g * 128 + t];
        q += g_psq[g * 128 + t];
    }
    float invN = 1.f / (float)N;
    float mu  = s * invN;
    float var = fmaxf(q * invN - mu * mu, 0.f);
    float sc  = rsqrtf(var + BN_EPS) * bn_g[t];
    g_scale[t] = sc;
    g_shift[t] = bn_b[t] - mu * sc;
}

// ---------------- K6: out = x + y0*scale + shift (REVERSED: reads y tail from L2) ----------------
__global__ void k_out(const float* __restrict__ x, float* __restrict__ out, int total4) {
    int idx = blockIdx.x * blockDim.x + threadIdx.x;
    if (idx >= total4) return;
    int i = total4 - 1 - idx;
    int j4 = i & 31;
    float4 sc = ((const float4*)g_scale)[j4];
    float4 sh = ((const float4*)g_shift)[j4];
    float4 xv = ((const float4*)x)[i];
    float4 yv = ((const float4*)g_y)[i];
    float4 o;
    o.x = xv.x + yv.x * sc.x + sh.x;
    o.y = xv.y + yv.y * sc.y + sh.y;
    o.z = xv.z + yv.z * sc.z + sh.z;
    o.w = xv.w + yv.w * sc.w + sh.w;
    ((float4*)out)[i] = o;
}

// ---------------- launch ----------------
extern "C" void kernel_launch(void* const* d_in, const int* in_sizes, int n_in,
                              void* d_out, int out_size) {
    const float* x     = (const float*)d_in[0];
    const int*   batch = (const int*)d_in[1];
    const float* pers0 = (const float*)d_in[2];
    const float* g1w   = (const float*)d_in[3];
    const float* g1b   = (const float*)d_in[4];
    const float* l1w   = (const float*)d_in[5];
    const float* g2w   = (const float*)d_in[6];
    const float* g2b   = (const float*)d_in[7];
    const float* l2w   = (const float*)d_in[8];
    const float* bng   = (const float*)d_in[9];
    const float* bnb   = (const float*)d_in[10];
    float* out = (float*)d_out;
    int N = in_sizes[0] / 128;

    cudaFuncSetAttribute(k_gemm1, cudaFuncAttributeMaxDynamicSharedMemorySize, SMEM_G1);
    cudaFuncSetAttribute(k_gemm2, cudaFuncAttributeMaxDynamicSharedMemorySize, SMEM_G2);

    k_bounds<<<(NG + 256) / 256, 256>>>(batch, N);
    k_lam1<<<NG, 288>>>(x, pers0, l1w, N);
    k_gemm1<<<NG, 256, SMEM_G1>>>(x, pers0, g1w, g1b, l2w, N);
    k_gemm2<<<NG, 256, SMEM_G2>>>(g2w, g2b, N);
    k_stats<<<1, 128>>>(bng, bnb, N);
    int total4 = N * 32;
    k_out<<<(total4 + 255) / 256, 256>>>(x, out, total4);
}